// round 12
// baseline (speedup 1.0000x reference)
#include <cuda_runtime.h>
#include <cstdint>

// ---------------------------------------------------------------------------
// NeuronCircuit: compress (MoE-weighted proj) -> causal MHA -> expand
// B=4 S=2048 D=1024 R=512 H=8 NC=NE=8 DH=64
//
// Round 11 -> 12: GEMM mainloop re-pipelined as a 3-stage cp.async ring with
// ONE __syncthreads per K-chunk (was 2-stage / 2 barriers -> tensor pipe 51%
// busy, issue 14%). Loads for chunk i+2 are issued after iter i's barrier
// (target stage was consumed at i-1 -> race-free). FUSEA keeps LDG-before-
// compute / STS-after-compute, now at distance 2. All else identical to R11.
// ---------------------------------------------------------------------------

#define Bz 4
#define Sz 2048
#define Dz 1024
#define Rz 512
#define Hz 8
#define NCz 8
#define DHz 64
#define Tz (Bz * Sz)          // 8192 tokens
#define PCOLS (NCz * Rz)      // 4096

// Scratch (device globals: allocation-free rule)
__device__ float g_P[(size_t)Tz * PCOLS];   // 134 MB (gemm1 output)
__device__ float g_Xr[(size_t)Tz * Dz];     // tf32-rounded x (32 MB)
__device__ float g_q[Tz * Rz];
__device__ float g_k[Tz * Rz];
__device__ float g_v[Tz * Rz];
__device__ float g_attn[Tz * Rz];
__device__ float g_wq[Tz * NCz];
__device__ float g_wk[Tz * NCz];
__device__ float g_wv[Tz * NCz];
__device__ float g_wo[Tz * NCz];
__device__ float g_CNt[(size_t)NCz * Rz * Dz];   // [NC][R][D]  (16 MB)
__device__ float g_ENt[(size_t)Dz * PCOLS];      // [D][NE*R]   (16 MB)

// ---------------------------------------------------------------------------
// Baseline-PTX helpers (valid on compute_103)
// ---------------------------------------------------------------------------
#define SW128(off) ((off) ^ (((off) >> 3) & 0x70))

__device__ __forceinline__ void cp_async16(void* smem_dst, const void* gmem_src) {
    uint32_t d = (uint32_t)__cvta_generic_to_shared(smem_dst);
    asm volatile("cp.async.cg.shared.global [%0], [%1], 16;"
                 :: "r"(d), "l"(gmem_src) : "memory");
}
#define CP_COMMIT() asm volatile("cp.async.commit_group;" ::: "memory")
#define CP_WAIT(n)  asm volatile("cp.async.wait_group %0;" :: "n"(n) : "memory")

__device__ __forceinline__ float tf32r(float x) {
    uint32_t r;
    asm("cvt.rna.tf32.f32 %0, %1;" : "=r"(r) : "f"(x));
    return __uint_as_float(r);
}

__device__ __forceinline__ void mma_tf32(float* d, const uint32_t* a, const uint32_t* b) {
    asm volatile(
        "mma.sync.aligned.m16n8k8.row.col.f32.tf32.tf32.f32 "
        "{%0,%1,%2,%3}, {%4,%5,%6,%7}, {%8,%9}, {%0,%1,%2,%3};"
        : "+f"(d[0]), "+f"(d[1]), "+f"(d[2]), "+f"(d[3])
        : "r"(a[0]), "r"(a[1]), "r"(a[2]), "r"(a[3]), "r"(b[0]), "r"(b[1]));
}

__device__ __forceinline__ void ldsm4(uint32_t (&r)[4], uint32_t addr) {
    asm volatile("ldmatrix.sync.aligned.m8n8.x4.shared.b16 {%0,%1,%2,%3}, [%4];"
                 : "=r"(r[0]), "=r"(r[1]), "=r"(r[2]), "=r"(r[3]) : "r"(addr));
}

// FFMA-only 2^y (y <= 0 after softmax-max subtraction), err ~2e-6
__device__ __forceinline__ float fexp2(float y) {
    y = fmaxf(y, -120.f);
    float tt = y + 12582912.f;                       // 1.5 * 2^23
    int i = __float_as_int(tt) - 0x4B400000;         // round(y)
    float f = y - (tt - 12582912.f);                 // frac in [-0.5, 0.5]
    float p =               1.3333558146428443e-3f;
    p = fmaf(p, f, 9.618129107628477e-3f);
    p = fmaf(p, f, 5.550410866482158e-2f);
    p = fmaf(p, f, 2.402265069591007e-1f);
    p = fmaf(p, f, 6.931471805599453e-1f);
    p = fmaf(p, f, 1.0f);
    return __int_as_float(__float_as_int(p) + (i << 23));
}

// ---------------------------------------------------------------------------
// Weight transpose (emits tf32-rounded values): out[c][r] = rnd(in[r][c])
// ---------------------------------------------------------------------------
__global__ __launch_bounds__(256) void transpose_kernel(
    const float* __restrict__ in, float* __restrict__ out,
    int rows, int cols, long zStride)
{
    __shared__ float tile[32][33];
    in  += (long)blockIdx.z * zStride;
    out += (long)blockIdx.z * zStride;
    const int c0 = blockIdx.x * 32;
    const int r0 = blockIdx.y * 32;
    const int tx = threadIdx.x & 31;
    const int ty = threadIdx.x >> 5;          // 0..7
#pragma unroll
    for (int j = 0; j < 32; j += 8)
        tile[ty + j][tx] = in[(long)(r0 + ty + j) * cols + c0 + tx];
    __syncthreads();
#pragma unroll
    for (int j = 0; j < 32; j += 8)
        out[(long)(c0 + ty + j) * rows + r0 + tx] = tf32r(tile[tx][ty + j]);
}

// ---------------------------------------------------------------------------
// tf32 mma.sync GEMM, 3-stage cp.async ring, ldmatrix fragment loads, SW128.
// C[M,N] = A[M,K] (row-major) x Bt[N,K] (K-major rows); CTA 128x128, BK=32,
// 8 warps (warp tile 64x32). One __syncthreads per chunk.
// FUSEA: A'[t, n*512+r] = tf32r(wo[t,n]*attn[t,r]) computed in the loader.
// ---------------------------------------------------------------------------
#define GEMM_STAGE_B 32768
#define GEMM_SMEM_TOTAL (3 * GEMM_STAGE_B)

template <bool FUSEA>
__global__ __launch_bounds__(256) void tf32_gemm(
    const float* __restrict__ A, const float* __restrict__ Bt,
    const float* __restrict__ wov,
    float* __restrict__ C, int K, int lda, int ldb, int ldc,
    long bStride, long cStride)
{
    extern __shared__ __align__(1024) char smem[];
    const int tid = threadIdx.x;
    const int wid = tid >> 5;
    const int lane = tid & 31;
    const int g = lane >> 2;
    const int t = lane & 3;
    const int warp_m = wid >> 2;
    const int warp_n = wid & 3;

    Bt += (long)blockIdx.z * bStride;
    C  += (long)blockIdx.z * cStride;
    const int brow = blockIdx.y * 128;
    const int bcol = blockIdx.x * 128;

    const float* Ab = A + (long)brow * lda;
    const float* Bb = Bt + (long)bcol * ldb;

    const int lrow = tid >> 1;
    const int lch4 = (tid & 1) << 2;

    auto loadB = [&](int k0, int s) {
        char* sB = smem + s * GEMM_STAGE_B + 16384;
        const float* gb = Bb + (long)lrow * ldb + k0 + (lch4 << 2);
#pragma unroll
        for (int c = 0; c < 4; c++) {
            const uint32_t off = SW128((uint32_t)((lrow << 7) + ((lch4 + c) << 4)));
            cp_async16(sB + off, gb + (c << 2));
        }
    };
    auto loadA_async = [&](int k0, int s) {
        char* sA = smem + s * GEMM_STAGE_B;
        const float* ga = Ab + (long)lrow * lda + k0 + (lch4 << 2);
#pragma unroll
        for (int c = 0; c < 4; c++) {
            const uint32_t off = SW128((uint32_t)((lrow << 7) + ((lch4 + c) << 4)));
            cp_async16(sA + off, ga + (c << 2));
        }
    };
    // FUSEA loaders: chunk [k0,k0+32) lies inside one expert n = k0>>9
    auto ldgA = [&](int k0, float4 (&ra)[4], float& wn) {
        const int n = k0 >> 9;
        const int r0 = k0 & 511;
        wn = __ldg(wov + (long)(brow + lrow) * 8 + n);
        const float* ga = Ab + (long)lrow * lda + r0 + (lch4 << 2);
#pragma unroll
        for (int c = 0; c < 4; c++)
            ra[c] = __ldg((const float4*)(ga + (c << 2)));
    };
    auto stsA = [&](int s, const float4 (&ra)[4], float wn) {
        char* sA = smem + s * GEMM_STAGE_B;
#pragma unroll
        for (int c = 0; c < 4; c++) {
            const uint32_t off = SW128((uint32_t)((lrow << 7) + ((lch4 + c) << 4)));
            *(float4*)(sA + off) = make_float4(
                tf32r(ra[c].x * wn), tf32r(ra[c].y * wn),
                tf32r(ra[c].z * wn), tf32r(ra[c].w * wn));
        }
    };

    // ldmatrix lane geometry (see R9)
    const int rowA = (((lane >> 3) & 1) << 3) + (lane & 7);
    const int colA = (lane >> 4) & 1;
    const int rowB = (((lane >> 4) & 1) << 3) + (lane & 7);
    const int colB = (lane >> 3) & 1;
    const uint32_t smem32 = (uint32_t)__cvta_generic_to_shared(smem);
    const uint32_t cAx = (uint32_t)(((colA << 4) ^ ((lane & 7) << 4)));
    const uint32_t cBx = (uint32_t)(((colB << 4) ^ ((lane & 7) << 4)));
    uint32_t aBase[4], bBase[2];
#pragma unroll
    for (int mt = 0; mt < 4; mt++)
        aBase[mt] = (uint32_t)((warp_m * 64 + mt * 16 + rowA) << 7);
#pragma unroll
    for (int np = 0; np < 2; np++)
        bBase[np] = (uint32_t)((warp_n * 32 + np * 16 + rowB) << 7) + 16384u;

    auto frag_ldsm = [&](uint32_t stage32, int ks,
                         uint32_t (&af)[4][4], uint32_t (&bf)[2][4]) {
        const uint32_t col = (uint32_t)(ks << 5);
#pragma unroll
        for (int mt = 0; mt < 4; mt++)
            ldsm4(af[mt], stage32 + aBase[mt] + (col ^ cAx));
#pragma unroll
        for (int np = 0; np < 2; np++)
            ldsm4(bf[np], stage32 + bBase[np] + (col ^ cBx));
    };

    float acc[4][4][4];
#pragma unroll
    for (int i = 0; i < 4; i++)
#pragma unroll
        for (int j = 0; j < 4; j++)
#pragma unroll
            for (int r = 0; r < 4; r++) acc[i][j][r] = 0.f;

    auto compute = [&](int i, int s) {
        const uint32_t stage32 = smem32 + (uint32_t)(s * GEMM_STAGE_B);
        uint32_t af[2][4][4];
        uint32_t bf[2][2][4];
        frag_ldsm(stage32, 0, af[0], bf[0]);
#pragma unroll
        for (int ks = 0; ks < 4; ks++) {
            if (ks < 3) frag_ldsm(stage32, ks + 1, af[(ks + 1) & 1], bf[(ks + 1) & 1]);
            const int cur = ks & 1;
#pragma unroll
            for (int mt = 0; mt < 4; mt++)
#pragma unroll
                for (int nt = 0; nt < 4; nt++)
                    mma_tf32(acc[mt][nt], af[cur][mt],
                             &bf[cur][nt >> 1][(nt & 1) << 1]);
        }
    };

    const int NCH = K >> 5;

    if (FUSEA) {
        float4 ra[4];
        float wn;
        // prologue: stages 0,1 (B groups g0,g1; A via LDG+STS)
        ldgA(0, ra, wn);
        loadB(0, 0); CP_COMMIT();
        stsA(0, ra, wn);
        if (NCH > 1) {
            ldgA(32, ra, wn);
            loadB(32, 1); CP_COMMIT();
            stsA(1, ra, wn);
        }
        int s = 0;
        for (int i = 0; i < NCH; i++) {
            if (i + 1 < NCH) { CP_WAIT(1); } else { CP_WAIT(0); }
            __syncthreads();                 // stage s ready; compute(i-1) done everywhere
            const bool pf = (i + 2 < NCH);
            const int s2 = (s + 2 >= 3) ? s - 1 : s + 2;
            if (pf) {
                ldgA((i + 2) << 5, ra, wn);  // LDG in flight over compute
                loadB((i + 2) << 5, s2); CP_COMMIT();
            }
            compute(i, s);
            if (pf) stsA(s2, ra, wn);        // LDG landed during compute
            s = (s + 1 == 3) ? 0 : s + 1;
        }
    } else {
        loadA_async(0, 0); loadB(0, 0); CP_COMMIT();
        if (NCH > 1) { loadA_async(32, 1); loadB(32, 1); CP_COMMIT(); }
        int s = 0;
        for (int i = 0; i < NCH; i++) {
            if (i + 1 < NCH) { CP_WAIT(1); } else { CP_WAIT(0); }
            __syncthreads();
            if (i + 2 < NCH) {
                const int s2 = (s + 2 >= 3) ? s - 1 : s + 2;
                loadA_async((i + 2) << 5, s2);
                loadB((i + 2) << 5, s2);
                CP_COMMIT();
            }
            compute(i, s);
            s = (s + 1 == 3) ? 0 : s + 1;
        }
    }

    // epilogue: c0,c1 at (row, col+2t), c2,c3 at (row+8, col+2t)
#pragma unroll
    for (int mt = 0; mt < 4; mt++) {
        const int row = brow + warp_m * 64 + mt * 16 + g;
#pragma unroll
        for (int nt = 0; nt < 4; nt++) {
            const int col = bcol + warp_n * 32 + nt * 8 + 2 * t;
            float* Cp = C + (long)row * ldc + col;
            *(float2*)Cp = make_float2(acc[mt][nt][0], acc[mt][nt][1]);
            *(float2*)(Cp + 8 * ldc) = make_float2(acc[mt][nt][2], acc[mt][nt][3]);
        }
    }
}

// ---------------------------------------------------------------------------
// Router; optionally also emits tf32-rounded x (compress pass: xrOut = Xr)
// ---------------------------------------------------------------------------
template <int DIM, int NR>
__global__ __launch_bounds__(256) void router_kernel(
    const float* __restrict__ x,
    const float* __restrict__ wr0, const float* __restrict__ wr1,
    const float* __restrict__ wr2,
    float* __restrict__ o0, float* __restrict__ o1, float* __restrict__ o2,
    float* __restrict__ xrOut)
{
    __shared__ float xs[DIM];
    __shared__ float lg[NR][8];
    const long t = blockIdx.x;
    const float4* xrow = (const float4*)(x + t * DIM);
    for (int i = threadIdx.x; i < DIM / 4; i += 256)
        ((float4*)xs)[i] = xrow[i];
    __syncthreads();

    if (xrOut) {
        float4* xo = (float4*)(xrOut + t * DIM);
        for (int i = threadIdx.x; i < DIM / 4; i += 256) {
            float4 v = ((const float4*)xs)[i];
            xo[i] = make_float4(tf32r(v.x), tf32r(v.y), tf32r(v.z), tf32r(v.w));
        }
    }

    const int w = threadIdx.x >> 5;
    const int lane = threadIdx.x & 31;
    const float* wrs[3] = {wr0, wr1, wr2};
#pragma unroll
    for (int rt = 0; rt < NR; rt++) {
        const float4* wv4 = (const float4*)(wrs[rt] + w * DIM);
        float s = 0.f;
#pragma unroll
        for (int i = lane; i < DIM / 4; i += 32) {
            float4 a = ((const float4*)xs)[i];
            float4 b = wv4[i];
            s += a.x * b.x + a.y * b.y + a.z * b.z + a.w * b.w;
        }
#pragma unroll
        for (int off = 16; off; off >>= 1)
            s += __shfl_xor_sync(0xffffffffu, s, off);
        if (lane == 0) lg[rt][w] = s;
    }
    __syncthreads();

    if (threadIdx.x < NR) {
        const int rt = threadIdx.x;
        float mx = lg[rt][0];
#pragma unroll
        for (int n = 1; n < 8; n++) mx = fmaxf(mx, lg[rt][n]);
        float e[8];
        float sum = 0.f;
#pragma unroll
        for (int n = 0; n < 8; n++) { e[n] = __expf(lg[rt][n] - mx); sum += e[n]; }
        const float inv = 1.f / sum;
        float* o = (rt == 0 ? o0 : (rt == 1 ? o1 : o2)) + t * 8;
#pragma unroll
        for (int n = 0; n < 8; n++) o[n] = e[n] * inv;
    }
}

// ---------------------------------------------------------------------------
// q/k/v[t,r] = tf32rnd( sum_n P[t, n*512 + r] * w{q,k,v}[t,n] )
// ---------------------------------------------------------------------------
__global__ __launch_bounds__(128) void reduce_qkv(
    const float* __restrict__ P,
    const float* __restrict__ wq, const float* __restrict__ wk,
    const float* __restrict__ wv,
    float* __restrict__ q, float* __restrict__ k, float* __restrict__ v)
{
    const long t = blockIdx.x;
    __shared__ float sq[8], sk[8], sv[8];
    if (threadIdx.x < 8) {
        sq[threadIdx.x] = wq[t * 8 + threadIdx.x];
        sk[threadIdx.x] = wk[t * 8 + threadIdx.x];
        sv[threadIdx.x] = wv[t * 8 + threadIdx.x];
    }
    __syncthreads();
    const float* Pt = P + t * PCOLS;
    for (int r = threadIdx.x; r < Rz; r += 128) {
        float aq = 0.f, ak = 0.f, av = 0.f;
#pragma unroll
        for (int n = 0; n < 8; n++) {
            float p = Pt[n * Rz + r];
            aq += p * sq[n];
            ak += p * sk[n];
            av += p * sv[n];
        }
        q[t * Rz + r] = tf32r(aq);
        k[t * Rz + r] = tf32r(ak);
        v[t * Rz + r] = tf32r(av);
    }
}

// ---------------------------------------------------------------------------
// Tensor-core causal flash attention (tf32 mma.sync). q/k/v pre-rounded.
// ---------------------------------------------------------------------------
#define PADT 68
#define ATTN_SMEM (3 * 64 * PADT * 4)
#define SCALE_L2E 0.1803368801111204f   // (1/sqrt(64)) * log2(e)

__global__ __launch_bounds__(128) void attn_tc_kernel(
    const float* __restrict__ q, const float* __restrict__ k,
    const float* __restrict__ v, float* __restrict__ out)
{
    extern __shared__ __align__(16) float sm[];
    float* Ks = sm;                    // [64][PADT]
    float* Vn = sm + 64 * PADT;        // [64][PADT]
    float* Ps = sm + 2 * 64 * PADT;    // [64][PADT], warp w owns rows w*16..+15

    const int bh = blockIdx.y;
    const int b = bh >> 3;
    const int h = bh & 7;
    const int qblk = gridDim.x - 1 - blockIdx.x;   // long blocks first
    const int qbase = qblk * 64;
    const int tid = threadIdx.x;
    const int w = tid >> 5;
    const int lane = tid & 31;
    const int g = lane >> 2;
    const int t = lane & 3;

    // Q fragments (already tf32-rounded)
    const float* qb = q + ((long)b * Sz + qbase + w * 16) * Rz + h * DHz;
    uint32_t qf[8][4];
#pragma unroll
    for (int ks = 0; ks < 8; ks++) {
        qf[ks][0] = __float_as_uint(qb[(long)g * Rz + 8 * ks + t]);
        qf[ks][1] = __float_as_uint(qb[(long)(g + 8) * Rz + 8 * ks + t]);
        qf[ks][2] = __float_as_uint(qb[(long)g * Rz + 8 * ks + t + 4]);
        qf[ks][3] = __float_as_uint(qb[(long)(g + 8) * Rz + 8 * ks + t + 4]);
    }

    float Oa[4][2][4];                  // [d-mtile][q-nfrag][regs], transposed
#pragma unroll
    for (int a = 0; a < 4; a++)
#pragma unroll
        for (int bb = 0; bb < 2; bb++)
#pragma unroll
            for (int c = 0; c < 4; c++) Oa[a][bb][c] = 0.f;
    float m_lo = -1e30f, m_hi = -1e30f, l_lo = 0.f, l_hi = 0.f;

    const float* kb = k + (long)b * Sz * Rz + h * DHz;
    const float* vb = v + (long)b * Sz * Rz + h * DHz;
    const int ntiles = qblk + 1;

    for (int tt = 0; tt < ntiles; tt++) {
        const int kvb = tt * 64;
        __syncthreads();
#pragma unroll
        for (int i = tid; i < 1024; i += 128) {
            const int row = i >> 4;
            const int col = (i & 15) << 2;
            *(float4*)(Ks + row * PADT + col) =
                *(const float4*)(kb + (long)(kvb + row) * Rz + col);
            *(float4*)(Vn + row * PADT + col) =
                *(const float4*)(vb + (long)(kvb + row) * Rz + col);
        }
        __syncthreads();

        // S = Q @ K^T : warp computes 16 x 64
        float S[8][4];
#pragma unroll
        for (int nf = 0; nf < 8; nf++)
#pragma unroll
            for (int c = 0; c < 4; c++) S[nf][c] = 0.f;
#pragma unroll
        for (int ks = 0; ks < 8; ks++) {
            const int c0 = 8 * ks + t, c1 = c0 + 4;
#pragma unroll
            for (int nf = 0; nf < 8; nf++) {
                uint32_t bfr[2];
                bfr[0] = __float_as_uint(Ks[(nf * 8 + g) * PADT + c0]);
                bfr[1] = __float_as_uint(Ks[(nf * 8 + g) * PADT + c1]);
                mma_tf32(S[nf], qf[ks], bfr);
            }
        }

        // causal mask on the diagonal tile
        if (tt == qblk) {
            const int rl = w * 16 + g, rh = rl + 8;
#pragma unroll
            for (int nf = 0; nf < 8; nf++) {
                const int c0 = nf * 8 + 2 * t;
                if (c0 > rl)     S[nf][0] = -1e30f;
                if (c0 + 1 > rl) S[nf][1] = -1e30f;
                if (c0 > rh)     S[nf][2] = -1e30f;
                if (c0 + 1 > rh) S[nf][3] = -1e30f;
            }
        }

        // online softmax (raw-score max; scale folded into exp2)
        float mx_lo = -1e30f, mx_hi = -1e30f;
#pragma unroll
        for (int nf = 0; nf < 8; nf++) {
            mx_lo = fmaxf(mx_lo, fmaxf(S[nf][0], S[nf][1]));
            mx_hi = fmaxf(mx_hi, fmaxf(S[nf][2], S[nf][3]));
        }
        mx_lo = fmaxf(mx_lo, __shfl_xor_sync(0xffffffffu, mx_lo, 1));
        mx_lo = fmaxf(mx_lo, __shfl_xor_sync(0xffffffffu, mx_lo, 2));
        mx_hi = fmaxf(mx_hi, __shfl_xor_sync(0xffffffffu, mx_hi, 1));
        mx_hi = fmaxf(mx_hi, __shfl_xor_sync(0xffffffffu, mx_hi, 2));

        const float mn_lo = fmaxf(m_lo, mx_lo);
        const float mn_hi = fmaxf(m_hi, mx_hi);
        const float corr_lo = fexp2((m_lo - mn_lo) * SCALE_L2E);
        const float corr_hi = fexp2((m_hi - mn_hi) * SCALE_L2E);
        m_lo = mn_lo; m_hi = mn_hi;
        l_lo *= corr_lo; l_hi *= corr_hi;

        float psum_lo = 0.f, psum_hi = 0.f;
        float* pw = Ps + (w * 16) * PADT;
#pragma unroll
        for (int nf = 0; nf < 8; nf++) {
            const int c0 = nf * 8 + 2 * t;
            float p0 = fexp2((S[nf][0] - mn_lo) * SCALE_L2E);
            float p1 = fexp2((S[nf][1] - mn_lo) * SCALE_L2E);
            float p2 = fexp2((S[nf][2] - mn_hi) * SCALE_L2E);
            float p3 = fexp2((S[nf][3] - mn_hi) * SCALE_L2E);
            psum_lo += p0 + p1;
            psum_hi += p2 + p3;
            *(float2*)(pw + g * PADT + c0) = make_float2(tf32r(p0), tf32r(p1));
            *(float2*)(pw + (g + 8) * PADT + c0) = make_float2(tf32r(p2), tf32r(p3));
        }
        psum_lo += __shfl_xor_sync(0xffffffffu, psum_lo, 1);
        psum_lo += __shfl_xor_sync(0xffffffffu, psum_lo, 2);
        psum_hi += __shfl_xor_sync(0xffffffffu, psum_hi, 1);
        psum_hi += __shfl_xor_sync(0xffffffffu, psum_hi, 2);
        l_lo += psum_lo; l_hi += psum_hi;

        // rescale O' by per-q-column corr (q col = nf2*8 + 2t / +1)
        {
            const float cA  = __shfl_sync(0xffffffffu, corr_lo, 8 * t);
            const float cA1 = __shfl_sync(0xffffffffu, corr_lo, 8 * t + 4);
            const float cB  = __shfl_sync(0xffffffffu, corr_hi, 8 * t);
            const float cB1 = __shfl_sync(0xffffffffu, corr_hi, 8 * t + 4);
#pragma unroll
            for (int mt = 0; mt < 4; mt++) {
                Oa[mt][0][0] *= cA;  Oa[mt][0][1] *= cA1;
                Oa[mt][0][2] *= cA;  Oa[mt][0][3] *= cA1;
                Oa[mt][1][0] *= cB;  Oa[mt][1][1] *= cB1;
                Oa[mt][1][2] *= cB;  Oa[mt][1][3] *= cB1;
            }
        }
        __syncwarp();

        // O' += V^T-as-A @ P-as-B : per warp 64d x 16q
#pragma unroll
        for (int ks = 0; ks < 8; ks++) {
            const int k0 = 8 * ks + t, k1 = k0 + 4;
            uint32_t bfr[2][2];
#pragma unroll
            for (int nf2 = 0; nf2 < 2; nf2++) {
                bfr[nf2][0] = __float_as_uint(pw[(nf2 * 8 + g) * PADT + k0]);
                bfr[nf2][1] = __float_as_uint(pw[(nf2 * 8 + g) * PADT + k1]);
            }
#pragma unroll
            for (int mt = 0; mt < 4; mt++) {
                uint32_t af[4];
                af[0] = __float_as_uint(Vn[k0 * PADT + mt * 16 + g]);
                af[1] = __float_as_uint(Vn[k0 * PADT + mt * 16 + g + 8]);
                af[2] = __float_as_uint(Vn[k1 * PADT + mt * 16 + g]);
                af[3] = __float_as_uint(Vn[k1 * PADT + mt * 16 + g + 8]);
                mma_tf32(Oa[mt][0], af, bfr[0]);
                mma_tf32(Oa[mt][1], af, bfr[1]);
            }
        }
        __syncwarp();
    }

    // normalize by 1/l per q column
    const float il_lo = 1.f / l_lo;
    const float il_hi = 1.f / l_hi;
    {
        const float iA  = __shfl_sync(0xffffffffu, il_lo, 8 * t);
        const float iA1 = __shfl_sync(0xffffffffu, il_lo, 8 * t + 4);
        const float iB  = __shfl_sync(0xffffffffu, il_hi, 8 * t);
        const float iB1 = __shfl_sync(0xffffffffu, il_hi, 8 * t + 4);
#pragma unroll
        for (int mt = 0; mt < 4; mt++) {
            Oa[mt][0][0] *= iA;  Oa[mt][0][1] *= iA1;
            Oa[mt][0][2] *= iA;  Oa[mt][0][3] *= iA1;
            Oa[mt][1][0] *= iB;  Oa[mt][1][1] *= iB1;
            Oa[mt][1][2] *= iB;  Oa[mt][1][3] *= iB1;
        }
    }

    // stage O' -> warp's smem region as [d][17-padded q] (scalar stores)
    float* osm = Ps + (w * 16) * PADT;   // 1088 floats, need 64*17=1086
    __syncwarp();
#pragma unroll
    for (int mt = 0; mt < 4; mt++) {
#pragma unroll
        for (int nf2 = 0; nf2 < 2; nf2++) {
            const int qc = nf2 * 8 + 2 * t;
            osm[(mt * 16 + g) * 17 + qc]         = Oa[mt][nf2][0];
            osm[(mt * 16 + g) * 17 + qc + 1]     = Oa[mt][nf2][1];
            osm[(mt * 16 + g + 8) * 17 + qc]     = Oa[mt][nf2][2];
            osm[(mt * 16 + g + 8) * 17 + qc + 1] = Oa[mt][nf2][3];
        }
    }
    __syncwarp();
    float* ob = out + ((long)b * Sz + qbase + w * 16) * Rz + h * DHz;
#pragma unroll
    for (int it = 0; it < 8; it++) {
        const int qr = it * 2 + (lane >> 4);
        const int d4 = (lane & 15) << 2;
        float4 vv;
        vv.x = osm[(d4 + 0) * 17 + qr];
        vv.y = osm[(d4 + 1) * 17 + qr];
        vv.z = osm[(d4 + 2) * 17 + qr];
        vv.w = osm[(d4 + 3) * 17 + qr];
        *(float4*)(ob + (long)qr * Rz + d4) = vv;
    }
}

// ---------------------------------------------------------------------------
extern "C" void kernel_launch(void* const* d_in, const int* in_sizes, int n_in,
                              void* d_out, int out_size)
{
    const float* x   = (const float*)d_in[0];
    // d_in[1] = mask: always causal tril -> applied analytically, not read
    const float* CN  = (const float*)d_in[2];  // [NC, D, R]
    const float* EN  = (const float*)d_in[3];  // [NE, R, D]
    const float* wrq = (const float*)d_in[4];
    const float* wrk = (const float*)d_in[5];
    const float* wrv = (const float*)d_in[6];
    const float* wro = (const float*)d_in[7];
    float* out = (float*)d_out;

    float *P, *Xr, *q, *k, *v, *attn, *wq, *wk, *wv, *wo, *CNt, *ENt;
    cudaGetSymbolAddress((void**)&P,    g_P);
    cudaGetSymbolAddress((void**)&Xr,   g_Xr);
    cudaGetSymbolAddress((void**)&q,    g_q);
    cudaGetSymbolAddress((void**)&k,    g_k);
    cudaGetSymbolAddress((void**)&v,    g_v);
    cudaGetSymbolAddress((void**)&attn, g_attn);
    cudaGetSymbolAddress((void**)&wq,   g_wq);
    cudaGetSymbolAddress((void**)&wk,   g_wk);
    cudaGetSymbolAddress((void**)&wv,   g_wv);
    cudaGetSymbolAddress((void**)&wo,   g_wo);
    cudaGetSymbolAddress((void**)&CNt,  g_CNt);
    cudaGetSymbolAddress((void**)&ENt,  g_ENt);

    cudaFuncSetAttribute(tf32_gemm<false>,
                         cudaFuncAttributeMaxDynamicSharedMemorySize, GEMM_SMEM_TOTAL);
    cudaFuncSetAttribute(tf32_gemm<true>,
                         cudaFuncAttributeMaxDynamicSharedMemorySize, GEMM_SMEM_TOTAL);
    cudaFuncSetAttribute(attn_tc_kernel,
                         cudaFuncAttributeMaxDynamicSharedMemorySize, ATTN_SMEM);

    // 0) pre-round weights (transposed)
    transpose_kernel<<<dim3(Rz / 32, Dz / 32, NCz), 256>>>(
        CN, CNt, Dz, Rz, (long)Dz * Rz);
    transpose_kernel<<<dim3(Dz / 32, PCOLS / 32, 1), 256>>>(
        EN, ENt, PCOLS, Dz, 0);

    // 1) compress routers (also emits tf32-rounded Xr)
    router_kernel<Dz, 3><<<Tz, 256>>>(x, wrq, wrk, wrv, wq, wk, wv, Xr);

    // 2) P = x @ compress_neurons
    tf32_gemm<false><<<dim3(Rz / 128, Tz / 128, NCz), 256, GEMM_SMEM_TOTAL>>>(
        Xr, CNt, nullptr, P, Dz, Dz, Dz, PCOLS, (long)Rz * Dz, (long)Rz);

    // 3) weighted reduce -> q,k,v (tf32-rounded)
    reduce_qkv<<<Tz, 128>>>(P, wq, wk, wv, q, k, v);

    // 4) causal attention (tensor cores)
    attn_tc_kernel<<<dim3(Sz / 64, Bz * Hz), 128, ATTN_SMEM>>>(q, k, v, attn);

    // 5) expand router
    router_kernel<Rz, 1><<<Tz, 256>>>(attn, wro, nullptr, nullptr,
                                      wo, nullptr, nullptr, nullptr);

    // 6+7) out = (wo (x) attn) @ expand_neurons  — A' fused into the loader
    tf32_gemm<true><<<dim3(Dz / 128, Tz / 128, 1), 256, GEMM_SMEM_TOTAL>>>(
        attn, ENt, wo, out, PCOLS, Rz, PCOLS, Dz, 0, 0);
}

// round 13
// speedup vs baseline: 1.5629x; 1.5629x over previous
#include <cuda_runtime.h>
#include <cstdint>

// ---------------------------------------------------------------------------
// NeuronCircuit: compress (MoE-weighted proj) -> causal MHA -> expand
// B=4 S=2048 D=1024 R=512 H=8 NC=NE=8 DH=64
//
// Round 12 -> 13:
//  * REVERT gemm to the R9 2-stage cp.async pipeline (3-stage ring regressed
//    444 -> 665 us; barrier theory falsified). buildA restored (R9 config
//    beat the fused-A R11 variant).
//  * KEEP router-emitted tf32 Xr (neutral-positive, saves a kernel).
//  * NEW: attention K/V tiles double-buffered via cp.async (prefetch tile
//    tt+1 over compute of tile tt; one wait + one barrier per tile).
// ---------------------------------------------------------------------------

#define Bz 4
#define Sz 2048
#define Dz 1024
#define Rz 512
#define Hz 8
#define NCz 8
#define DHz 64
#define Tz (Bz * Sz)          // 8192 tokens
#define PCOLS (NCz * Rz)      // 4096

// Scratch (device globals: allocation-free rule)
__device__ float g_P[(size_t)Tz * PCOLS];   // 134 MB, reused as A' for expand
__device__ float g_Xr[(size_t)Tz * Dz];     // tf32-rounded x (32 MB)
__device__ float g_q[Tz * Rz];
__device__ float g_k[Tz * Rz];
__device__ float g_v[Tz * Rz];
__device__ float g_attn[Tz * Rz];
__device__ float g_wq[Tz * NCz];
__device__ float g_wk[Tz * NCz];
__device__ float g_wv[Tz * NCz];
__device__ float g_wo[Tz * NCz];
__device__ float g_CNt[(size_t)NCz * Rz * Dz];   // [NC][R][D]  (16 MB)
__device__ float g_ENt[(size_t)Dz * PCOLS];      // [D][NE*R]   (16 MB)

// ---------------------------------------------------------------------------
// Baseline-PTX helpers (valid on compute_103)
// ---------------------------------------------------------------------------
#define SW128(off) ((off) ^ (((off) >> 3) & 0x70))

__device__ __forceinline__ void cp_async16(void* smem_dst, const void* gmem_src) {
    uint32_t d = (uint32_t)__cvta_generic_to_shared(smem_dst);
    asm volatile("cp.async.cg.shared.global [%0], [%1], 16;"
                 :: "r"(d), "l"(gmem_src) : "memory");
}
#define CP_COMMIT() asm volatile("cp.async.commit_group;" ::: "memory")
#define CP_WAIT(n)  asm volatile("cp.async.wait_group %0;" :: "n"(n) : "memory")

__device__ __forceinline__ float tf32r(float x) {
    uint32_t r;
    asm("cvt.rna.tf32.f32 %0, %1;" : "=r"(r) : "f"(x));
    return __uint_as_float(r);
}

__device__ __forceinline__ void mma_tf32(float* d, const uint32_t* a, const uint32_t* b) {
    asm volatile(
        "mma.sync.aligned.m16n8k8.row.col.f32.tf32.tf32.f32 "
        "{%0,%1,%2,%3}, {%4,%5,%6,%7}, {%8,%9}, {%0,%1,%2,%3};"
        : "+f"(d[0]), "+f"(d[1]), "+f"(d[2]), "+f"(d[3])
        : "r"(a[0]), "r"(a[1]), "r"(a[2]), "r"(a[3]), "r"(b[0]), "r"(b[1]));
}

__device__ __forceinline__ void ldsm4(uint32_t (&r)[4], uint32_t addr) {
    asm volatile("ldmatrix.sync.aligned.m8n8.x4.shared.b16 {%0,%1,%2,%3}, [%4];"
                 : "=r"(r[0]), "=r"(r[1]), "=r"(r[2]), "=r"(r[3]) : "r"(addr));
}

// FFMA-only 2^y (y <= 0 after softmax-max subtraction), err ~2e-6
__device__ __forceinline__ float fexp2(float y) {
    y = fmaxf(y, -120.f);
    float tt = y + 12582912.f;                       // 1.5 * 2^23
    int i = __float_as_int(tt) - 0x4B400000;         // round(y)
    float f = y - (tt - 12582912.f);                 // frac in [-0.5, 0.5]
    float p =               1.3333558146428443e-3f;
    p = fmaf(p, f, 9.618129107628477e-3f);
    p = fmaf(p, f, 5.550410866482158e-2f);
    p = fmaf(p, f, 2.402265069591007e-1f);
    p = fmaf(p, f, 6.931471805599453e-1f);
    p = fmaf(p, f, 1.0f);
    return __int_as_float(__float_as_int(p) + (i << 23));
}

// ---------------------------------------------------------------------------
// Weight transpose (emits tf32-rounded values): out[c][r] = rnd(in[r][c])
// ---------------------------------------------------------------------------
__global__ __launch_bounds__(256) void transpose_kernel(
    const float* __restrict__ in, float* __restrict__ out,
    int rows, int cols, long zStride)
{
    __shared__ float tile[32][33];
    in  += (long)blockIdx.z * zStride;
    out += (long)blockIdx.z * zStride;
    const int c0 = blockIdx.x * 32;
    const int r0 = blockIdx.y * 32;
    const int tx = threadIdx.x & 31;
    const int ty = threadIdx.x >> 5;          // 0..7
#pragma unroll
    for (int j = 0; j < 32; j += 8)
        tile[ty + j][tx] = in[(long)(r0 + ty + j) * cols + c0 + tx];
    __syncthreads();
#pragma unroll
    for (int j = 0; j < 32; j += 8)
        out[(long)(c0 + ty + j) * rows + r0 + tx] = tf32r(tile[tx][ty + j]);
}

// ---------------------------------------------------------------------------
// tf32 mma.sync GEMM — EXACT R9 pipeline (2-stage cp.async, ldmatrix, SW128).
// C[M,N] = A[M,K] (row-major) x Bt[N,K] (K-major rows); CTA 128x128, BK=32,
// 8 warps (warp tile 64x32).
// ---------------------------------------------------------------------------
#define GEMM_SMEM_TOTAL (2 * 32768)

__global__ __launch_bounds__(256) void tf32_gemm(
    const float* __restrict__ A, const float* __restrict__ Bt,
    float* __restrict__ C, int K, int lda, int ldb, int ldc,
    long bStride, long cStride)
{
    extern __shared__ __align__(1024) char smem[];
    const int tid = threadIdx.x;
    const int wid = tid >> 5;
    const int lane = tid & 31;
    const int g = lane >> 2;
    const int t = lane & 3;
    const int warp_m = wid >> 2;
    const int warp_n = wid & 3;

    Bt += (long)blockIdx.z * bStride;
    C  += (long)blockIdx.z * cStride;
    const int brow = blockIdx.y * 128;
    const int bcol = blockIdx.x * 128;

    const float* Ab = A + (long)brow * lda;
    const float* Bb = Bt + (long)bcol * ldb;

    const int lrow = tid >> 1;
    const int lch4 = (tid & 1) << 2;
    auto load_chunk = [&](int k0, int s) {
        char* sA = smem + s * 32768;
        char* sB = sA + 16384;
        const float* ga = Ab + (long)lrow * lda + k0 + (lch4 << 2);
        const float* gb = Bb + (long)lrow * ldb + k0 + (lch4 << 2);
#pragma unroll
        for (int c = 0; c < 4; c++) {
            const uint32_t off = SW128((uint32_t)((lrow << 7) + ((lch4 + c) << 4)));
            cp_async16(sA + off, ga + (c << 2));
            cp_async16(sB + off, gb + (c << 2));
        }
    };

    const int rowA = (((lane >> 3) & 1) << 3) + (lane & 7);
    const int colA = (lane >> 4) & 1;
    const int rowB = (((lane >> 4) & 1) << 3) + (lane & 7);
    const int colB = (lane >> 3) & 1;
    const uint32_t smem32 = (uint32_t)__cvta_generic_to_shared(smem);
    const uint32_t cAx = (uint32_t)(((colA << 4) ^ ((lane & 7) << 4)));
    const uint32_t cBx = (uint32_t)(((colB << 4) ^ ((lane & 7) << 4)));
    uint32_t aBase[4], bBase[2];
#pragma unroll
    for (int mt = 0; mt < 4; mt++)
        aBase[mt] = (uint32_t)((warp_m * 64 + mt * 16 + rowA) << 7);
#pragma unroll
    for (int np = 0; np < 2; np++)
        bBase[np] = (uint32_t)((warp_n * 32 + np * 16 + rowB) << 7) + 16384u;

    auto frag_ldsm = [&](uint32_t stage32, int ks,
                         uint32_t (&af)[4][4], uint32_t (&bf)[2][4]) {
        const uint32_t col = (uint32_t)(ks << 5);
#pragma unroll
        for (int mt = 0; mt < 4; mt++)
            ldsm4(af[mt], stage32 + aBase[mt] + (col ^ cAx));
#pragma unroll
        for (int np = 0; np < 2; np++)
            ldsm4(bf[np], stage32 + bBase[np] + (col ^ cBx));
    };

    float acc[4][4][4];
#pragma unroll
    for (int i = 0; i < 4; i++)
#pragma unroll
        for (int j = 0; j < 4; j++)
#pragma unroll
            for (int r = 0; r < 4; r++) acc[i][j][r] = 0.f;

    const int NCH = K >> 5;
    load_chunk(0, 0);
    CP_COMMIT();

    for (int i = 0; i < NCH; i++) {
        if (i + 1 < NCH) {
            load_chunk((i + 1) << 5, (i + 1) & 1);
            CP_COMMIT();
            CP_WAIT(1);
        } else {
            CP_WAIT(0);
        }
        __syncthreads();

        const uint32_t stage32 = smem32 + (uint32_t)((i & 1) * 32768);

        uint32_t af[2][4][4];
        uint32_t bf[2][2][4];
        frag_ldsm(stage32, 0, af[0], bf[0]);
#pragma unroll
        for (int ks = 0; ks < 4; ks++) {
            if (ks < 3) frag_ldsm(stage32, ks + 1, af[(ks + 1) & 1], bf[(ks + 1) & 1]);
            const int cur = ks & 1;
#pragma unroll
            for (int mt = 0; mt < 4; mt++)
#pragma unroll
                for (int nt = 0; nt < 4; nt++)
                    mma_tf32(acc[mt][nt], af[cur][mt],
                             &bf[cur][nt >> 1][(nt & 1) << 1]);
        }
        __syncthreads();
    }

#pragma unroll
    for (int mt = 0; mt < 4; mt++) {
        const int row = brow + warp_m * 64 + mt * 16 + g;
#pragma unroll
        for (int nt = 0; nt < 4; nt++) {
            const int col = bcol + warp_n * 32 + nt * 8 + 2 * t;
            float* Cp = C + (long)row * ldc + col;
            *(float2*)Cp = make_float2(acc[mt][nt][0], acc[mt][nt][1]);
            *(float2*)(Cp + 8 * ldc) = make_float2(acc[mt][nt][2], acc[mt][nt][3]);
        }
    }
}

// ---------------------------------------------------------------------------
// Router; optionally also emits tf32-rounded x (compress pass: xrOut = Xr)
// ---------------------------------------------------------------------------
template <int DIM, int NR>
__global__ __launch_bounds__(256) void router_kernel(
    const float* __restrict__ x,
    const float* __restrict__ wr0, const float* __restrict__ wr1,
    const float* __restrict__ wr2,
    float* __restrict__ o0, float* __restrict__ o1, float* __restrict__ o2,
    float* __restrict__ xrOut)
{
    __shared__ float xs[DIM];
    __shared__ float lg[NR][8];
    const long t = blockIdx.x;
    const float4* xrow = (const float4*)(x + t * DIM);
    for (int i = threadIdx.x; i < DIM / 4; i += 256)
        ((float4*)xs)[i] = xrow[i];
    __syncthreads();

    if (xrOut) {
        float4* xo = (float4*)(xrOut + t * DIM);
        for (int i = threadIdx.x; i < DIM / 4; i += 256) {
            float4 v = ((const float4*)xs)[i];
            xo[i] = make_float4(tf32r(v.x), tf32r(v.y), tf32r(v.z), tf32r(v.w));
        }
    }

    const int w = threadIdx.x >> 5;
    const int lane = threadIdx.x & 31;
    const float* wrs[3] = {wr0, wr1, wr2};
#pragma unroll
    for (int rt = 0; rt < NR; rt++) {
        const float4* wv4 = (const float4*)(wrs[rt] + w * DIM);
        float s = 0.f;
#pragma unroll
        for (int i = lane; i < DIM / 4; i += 32) {
            float4 a = ((const float4*)xs)[i];
            float4 b = wv4[i];
            s += a.x * b.x + a.y * b.y + a.z * b.z + a.w * b.w;
        }
#pragma unroll
        for (int off = 16; off; off >>= 1)
            s += __shfl_xor_sync(0xffffffffu, s, off);
        if (lane == 0) lg[rt][w] = s;
    }
    __syncthreads();

    if (threadIdx.x < NR) {
        const int rt = threadIdx.x;
        float mx = lg[rt][0];
#pragma unroll
        for (int n = 1; n < 8; n++) mx = fmaxf(mx, lg[rt][n]);
        float e[8];
        float sum = 0.f;
#pragma unroll
        for (int n = 0; n < 8; n++) { e[n] = __expf(lg[rt][n] - mx); sum += e[n]; }
        const float inv = 1.f / sum;
        float* o = (rt == 0 ? o0 : (rt == 1 ? o1 : o2)) + t * 8;
#pragma unroll
        for (int n = 0; n < 8; n++) o[n] = e[n] * inv;
    }
}

// ---------------------------------------------------------------------------
// q/k/v[t,r] = tf32rnd( sum_n P[t, n*512 + r] * w{q,k,v}[t,n] )
// ---------------------------------------------------------------------------
__global__ __launch_bounds__(128) void reduce_qkv(
    const float* __restrict__ P,
    const float* __restrict__ wq, const float* __restrict__ wk,
    const float* __restrict__ wv,
    float* __restrict__ q, float* __restrict__ k, float* __restrict__ v)
{
    const long t = blockIdx.x;
    __shared__ float sq[8], sk[8], sv[8];
    if (threadIdx.x < 8) {
        sq[threadIdx.x] = wq[t * 8 + threadIdx.x];
        sk[threadIdx.x] = wk[t * 8 + threadIdx.x];
        sv[threadIdx.x] = wv[t * 8 + threadIdx.x];
    }
    __syncthreads();
    const float* Pt = P + t * PCOLS;
    for (int r = threadIdx.x; r < Rz; r += 128) {
        float aq = 0.f, ak = 0.f, av = 0.f;
#pragma unroll
        for (int n = 0; n < 8; n++) {
            float p = Pt[n * Rz + r];
            aq += p * sq[n];
            ak += p * sk[n];
            av += p * sv[n];
        }
        q[t * Rz + r] = tf32r(aq);
        k[t * Rz + r] = tf32r(ak);
        v[t * Rz + r] = tf32r(av);
    }
}

// ---------------------------------------------------------------------------
// Tensor-core causal flash attention (tf32 mma.sync), q/k/v pre-rounded.
// K/V tiles double-buffered with cp.async: prefetch tile tt+1 during compute
// of tile tt. One CP_WAIT + one __syncthreads per tile.
// smem: KV stage s at  s*(2*64*PADT)  (Ks then Vn), Ps after both stages.
// ---------------------------------------------------------------------------
#define PADT 68
#define KVSTAGE (2 * 64 * PADT)              // floats per stage (Ks+Vn)
#define ATTN_SMEM ((2 * KVSTAGE + 64 * PADT) * 4)
#define SCALE_L2E 0.1803368801111204f        // (1/sqrt(64)) * log2(e)

__global__ __launch_bounds__(128) void attn_tc_kernel(
    const float* __restrict__ q, const float* __restrict__ k,
    const float* __restrict__ v, float* __restrict__ out)
{
    extern __shared__ __align__(16) float sm[];
    float* Ps = sm + 2 * KVSTAGE;      // [64][PADT], warp w owns rows w*16..+15

    const int bh = blockIdx.y;
    const int b = bh >> 3;
    const int h = bh & 7;
    const int qblk = gridDim.x - 1 - blockIdx.x;   // long blocks first
    const int qbase = qblk * 64;
    const int tid = threadIdx.x;
    const int w = tid >> 5;
    const int lane = tid & 31;
    const int g = lane >> 2;
    const int t = lane & 3;

    // Q fragments (already tf32-rounded)
    const float* qb = q + ((long)b * Sz + qbase + w * 16) * Rz + h * DHz;
    uint32_t qf[8][4];
#pragma unroll
    for (int ks = 0; ks < 8; ks++) {
        qf[ks][0] = __float_as_uint(qb[(long)g * Rz + 8 * ks + t]);
        qf[ks][1] = __float_as_uint(qb[(long)(g + 8) * Rz + 8 * ks + t]);
        qf[ks][2] = __float_as_uint(qb[(long)g * Rz + 8 * ks + t + 4]);
        qf[ks][3] = __float_as_uint(qb[(long)(g + 8) * Rz + 8 * ks + t + 4]);
    }

    float Oa[4][2][4];                  // [d-mtile][q-nfrag][regs], transposed
#pragma unroll
    for (int a = 0; a < 4; a++)
#pragma unroll
        for (int bb = 0; bb < 2; bb++)
#pragma unroll
            for (int c = 0; c < 4; c++) Oa[a][bb][c] = 0.f;
    float m_lo = -1e30f, m_hi = -1e30f, l_lo = 0.f, l_hi = 0.f;

    const float* kb = k + (long)b * Sz * Rz + h * DHz;
    const float* vb = v + (long)b * Sz * Rz + h * DHz;
    const int ntiles = qblk + 1;

    // cp.async K/V tile loader into stage s
    auto loadKV = [&](int tile, int s) {
        float* Kd = sm + s * KVSTAGE;
        float* Vd = Kd + 64 * PADT;
        const long base = (long)(tile * 64);
#pragma unroll
        for (int i = tid; i < 1024; i += 128) {
            const int row = i >> 4;
            const int col = (i & 15) << 2;
            cp_async16(Kd + row * PADT + col, kb + (base + row) * Rz + col);
            cp_async16(Vd + row * PADT + col, vb + (base + row) * Rz + col);
        }
    };

    loadKV(0, 0);
    CP_COMMIT();

    for (int tt = 0; tt < ntiles; tt++) {
        const int s = tt & 1;
        CP_WAIT(0);
        __syncthreads();   // stage s visible to all; compute(tt-1) done -> s^1 free
        if (tt + 1 < ntiles) {
            loadKV(tt + 1, s ^ 1);
            CP_COMMIT();
        }
        const float* Ks = sm + s * KVSTAGE;
        const float* Vn = Ks + 64 * PADT;

        // S = Q @ K^T : warp computes 16 x 64
        float S[8][4];
#pragma unroll
        for (int nf = 0; nf < 8; nf++)
#pragma unroll
            for (int c = 0; c < 4; c++) S[nf][c] = 0.f;
#pragma unroll
        for (int ks = 0; ks < 8; ks++) {
            const int c0 = 8 * ks + t, c1 = c0 + 4;
#pragma unroll
            for (int nf = 0; nf < 8; nf++) {
                uint32_t bfr[2];
                bfr[0] = __float_as_uint(Ks[(nf * 8 + g) * PADT + c0]);
                bfr[1] = __float_as_uint(Ks[(nf * 8 + g) * PADT + c1]);
                mma_tf32(S[nf], qf[ks], bfr);
            }
        }

        // causal mask on the diagonal tile
        if (tt == qblk) {
            const int rl = w * 16 + g, rh = rl + 8;
#pragma unroll
            for (int nf = 0; nf < 8; nf++) {
                const int c0 = nf * 8 + 2 * t;
                if (c0 > rl)     S[nf][0] = -1e30f;
                if (c0 + 1 > rl) S[nf][1] = -1e30f;
                if (c0 > rh)     S[nf][2] = -1e30f;
                if (c0 + 1 > rh) S[nf][3] = -1e30f;
            }
        }

        // online softmax (raw-score max; scale folded into exp2)
        float mx_lo = -1e30f, mx_hi = -1e30f;
#pragma unroll
        for (int nf = 0; nf < 8; nf++) {
            mx_lo = fmaxf(mx_lo, fmaxf(S[nf][0], S[nf][1]));
            mx_hi = fmaxf(mx_hi, fmaxf(S[nf][2], S[nf][3]));
        }
        mx_lo = fmaxf(mx_lo, __shfl_xor_sync(0xffffffffu, mx_lo, 1));
        mx_lo = fmaxf(mx_lo, __shfl_xor_sync(0xffffffffu, mx_lo, 2));
        mx_hi = fmaxf(mx_hi, __shfl_xor_sync(0xffffffffu, mx_hi, 1));
        mx_hi = fmaxf(mx_hi, __shfl_xor_sync(0xffffffffu, mx_hi, 2));

        const float mn_lo = fmaxf(m_lo, mx_lo);
        const float mn_hi = fmaxf(m_hi, mx_hi);
        const float corr_lo = fexp2((m_lo - mn_lo) * SCALE_L2E);
        const float corr_hi = fexp2((m_hi - mn_hi) * SCALE_L2E);
        m_lo = mn_lo; m_hi = mn_hi;
        l_lo *= corr_lo; l_hi *= corr_hi;

        float psum_lo = 0.f, psum_hi = 0.f;
        float* pw = Ps + (w * 16) * PADT;
#pragma unroll
        for (int nf = 0; nf < 8; nf++) {
            const int c0 = nf * 8 + 2 * t;
            float p0 = fexp2((S[nf][0] - mn_lo) * SCALE_L2E);
            float p1 = fexp2((S[nf][1] - mn_lo) * SCALE_L2E);
            float p2 = fexp2((S[nf][2] - mn_hi) * SCALE_L2E);
            float p3 = fexp2((S[nf][3] - mn_hi) * SCALE_L2E);
            psum_lo += p0 + p1;
            psum_hi += p2 + p3;
            *(float2*)(pw + g * PADT + c0) = make_float2(tf32r(p0), tf32r(p1));
            *(float2*)(pw + (g + 8) * PADT + c0) = make_float2(tf32r(p2), tf32r(p3));
        }
        psum_lo += __shfl_xor_sync(0xffffffffu, psum_lo, 1);
        psum_lo += __shfl_xor_sync(0xffffffffu, psum_lo, 2);
        psum_hi += __shfl_xor_sync(0xffffffffu, psum_hi, 1);
        psum_hi += __shfl_xor_sync(0xffffffffu, psum_hi, 2);
        l_lo += psum_lo; l_hi += psum_hi;

        // rescale O' by per-q-column corr (q col = nf2*8 + 2t / +1)
        {
            const float cA  = __shfl_sync(0xffffffffu, corr_lo, 8 * t);
            const float cA1 = __shfl_sync(0xffffffffu, corr_lo, 8 * t + 4);
            const float cB  = __shfl_sync(0xffffffffu, corr_hi, 8 * t);
            const float cB1 = __shfl_sync(0xffffffffu, corr_hi, 8 * t + 4);
#pragma unroll
            for (int mt = 0; mt < 4; mt++) {
                Oa[mt][0][0] *= cA;  Oa[mt][0][1] *= cA1;
                Oa[mt][0][2] *= cA;  Oa[mt][0][3] *= cA1;
                Oa[mt][1][0] *= cB;  Oa[mt][1][1] *= cB1;
                Oa[mt][1][2] *= cB;  Oa[mt][1][3] *= cB1;
            }
        }
        __syncwarp();

        // O' += V^T-as-A @ P-as-B : per warp 64d x 16q
#pragma unroll
        for (int ks = 0; ks < 8; ks++) {
            const int k0 = 8 * ks + t, k1 = k0 + 4;
            uint32_t bfr[2][2];
#pragma unroll
            for (int nf2 = 0; nf2 < 2; nf2++) {
                bfr[nf2][0] = __float_as_uint(pw[(nf2 * 8 + g) * PADT + k0]);
                bfr[nf2][1] = __float_as_uint(pw[(nf2 * 8 + g) * PADT + k1]);
            }
#pragma unroll
            for (int mt = 0; mt < 4; mt++) {
                uint32_t af[4];
                af[0] = __float_as_uint(Vn[k0 * PADT + mt * 16 + g]);
                af[1] = __float_as_uint(Vn[k0 * PADT + mt * 16 + g + 8]);
                af[2] = __float_as_uint(Vn[k1 * PADT + mt * 16 + g]);
                af[3] = __float_as_uint(Vn[k1 * PADT + mt * 16 + g + 8]);
                mma_tf32(Oa[mt][0], af, bfr[0]);
                mma_tf32(Oa[mt][1], af, bfr[1]);
            }
        }
        __syncwarp();
    }

    // normalize by 1/l per q column
    const float il_lo = 1.f / l_lo;
    const float il_hi = 1.f / l_hi;
    {
        const float iA  = __shfl_sync(0xffffffffu, il_lo, 8 * t);
        const float iA1 = __shfl_sync(0xffffffffu, il_lo, 8 * t + 4);
        const float iB  = __shfl_sync(0xffffffffu, il_hi, 8 * t);
        const float iB1 = __shfl_sync(0xffffffffu, il_hi, 8 * t + 4);
#pragma unroll
        for (int mt = 0; mt < 4; mt++) {
            Oa[mt][0][0] *= iA;  Oa[mt][0][1] *= iA1;
            Oa[mt][0][2] *= iA;  Oa[mt][0][3] *= iA1;
            Oa[mt][1][0] *= iB;  Oa[mt][1][1] *= iB1;
            Oa[mt][1][2] *= iB;  Oa[mt][1][3] *= iB1;
        }
    }

    // stage O' -> warp's smem region as [d][17-padded q] (scalar stores)
    float* osm = Ps + (w * 16) * PADT;   // 1088 floats, need 64*17=1086
    __syncwarp();
#pragma unroll
    for (int mt = 0; mt < 4; mt++) {
#pragma unroll
        for (int nf2 = 0; nf2 < 2; nf2++) {
            const int qc = nf2 * 8 + 2 * t;
            osm[(mt * 16 + g) * 17 + qc]         = Oa[mt][nf2][0];
            osm[(mt * 16 + g) * 17 + qc + 1]     = Oa[mt][nf2][1];
            osm[(mt * 16 + g + 8) * 17 + qc]     = Oa[mt][nf2][2];
            osm[(mt * 16 + g + 8) * 17 + qc + 1] = Oa[mt][nf2][3];
        }
    }
    __syncwarp();
    float* ob = out + ((long)b * Sz + qbase + w * 16) * Rz + h * DHz;
#pragma unroll
    for (int it = 0; it < 8; it++) {
        const int qr = it * 2 + (lane >> 4);
        const int d4 = (lane & 15) << 2;
        float4 vv;
        vv.x = osm[(d4 + 0) * 17 + qr];
        vv.y = osm[(d4 + 1) * 17 + qr];
        vv.z = osm[(d4 + 2) * 17 + qr];
        vv.w = osm[(d4 + 3) * 17 + qr];
        *(float4*)(ob + (long)qr * Rz + d4) = vv;
    }
}

// ---------------------------------------------------------------------------
// A'[t, n*512 + r] = rnd(wo[t,n] * attn[t,r])  (pre-rounded for GEMM2)
// ---------------------------------------------------------------------------
__global__ __launch_bounds__(256) void build_expand_A(
    const float* __restrict__ attn, const float* __restrict__ wo,
    float* __restrict__ Aout)
{
    __shared__ float as_[Rz];
    __shared__ float ws[8];
    const long t = blockIdx.x;
    for (int i = threadIdx.x; i < Rz / 4; i += 256)
        ((float4*)as_)[i] = ((const float4*)(attn + t * Rz))[i];
    if (threadIdx.x < 8) ws[threadIdx.x] = wo[t * 8 + threadIdx.x];
    __syncthreads();
    for (int i = threadIdx.x; i < (8 * Rz / 4); i += 256) {
        int n = i >> 7;
        int r4 = i & 127;
        float4 a = ((float4*)as_)[r4];
        float wn = ws[n];
        ((float4*)(Aout + t * PCOLS + n * Rz))[r4] =
            make_float4(tf32r(a.x * wn), tf32r(a.y * wn),
                        tf32r(a.z * wn), tf32r(a.w * wn));
    }
}

// ---------------------------------------------------------------------------
extern "C" void kernel_launch(void* const* d_in, const int* in_sizes, int n_in,
                              void* d_out, int out_size)
{
    const float* x   = (const float*)d_in[0];
    // d_in[1] = mask: always causal tril -> applied analytically, not read
    const float* CN  = (const float*)d_in[2];  // [NC, D, R]
    const float* EN  = (const float*)d_in[3];  // [NE, R, D]
    const float* wrq = (const float*)d_in[4];
    const float* wrk = (const float*)d_in[5];
    const float* wrv = (const float*)d_in[6];
    const float* wro = (const float*)d_in[7];
    float* out = (float*)d_out;

    float *P, *Xr, *q, *k, *v, *attn, *wq, *wk, *wv, *wo, *CNt, *ENt;
    cudaGetSymbolAddress((void**)&P,    g_P);
    cudaGetSymbolAddress((void**)&Xr,   g_Xr);
    cudaGetSymbolAddress((void**)&q,    g_q);
    cudaGetSymbolAddress((void**)&k,    g_k);
    cudaGetSymbolAddress((void**)&v,    g_v);
    cudaGetSymbolAddress((void**)&attn, g_attn);
    cudaGetSymbolAddress((void**)&wq,   g_wq);
    cudaGetSymbolAddress((void**)&wk,   g_wk);
    cudaGetSymbolAddress((void**)&wv,   g_wv);
    cudaGetSymbolAddress((void**)&wo,   g_wo);
    cudaGetSymbolAddress((void**)&CNt,  g_CNt);
    cudaGetSymbolAddress((void**)&ENt,  g_ENt);

    cudaFuncSetAttribute(tf32_gemm,
                         cudaFuncAttributeMaxDynamicSharedMemorySize, GEMM_SMEM_TOTAL);
    cudaFuncSetAttribute(attn_tc_kernel,
                         cudaFuncAttributeMaxDynamicSharedMemorySize, ATTN_SMEM);

    // 0) pre-round weights (transposed)
    transpose_kernel<<<dim3(Rz / 32, Dz / 32, NCz), 256>>>(
        CN, CNt, Dz, Rz, (long)Dz * Rz);
    transpose_kernel<<<dim3(Dz / 32, PCOLS / 32, 1), 256>>>(
        EN, ENt, PCOLS, Dz, 0);

    // 1) compress routers (also emits tf32-rounded Xr)
    router_kernel<Dz, 3><<<Tz, 256>>>(x, wrq, wrk, wrv, wq, wk, wv, Xr);

    // 2) P = x @ compress_neurons
    tf32_gemm<<<dim3(Rz / 128, Tz / 128, NCz), 256, GEMM_SMEM_TOTAL>>>(
        Xr, CNt, P, Dz, Dz, Dz, PCOLS, (long)Rz * Dz, (long)Rz);

    // 3) weighted reduce -> q,k,v (tf32-rounded)
    reduce_qkv<<<Tz, 128>>>(P, wq, wk, wv, q, k, v);

    // 4) causal attention (tensor cores, cp.async K/V pipeline)
    attn_tc_kernel<<<dim3(Sz / 64, Bz * Hz), 128, ATTN_SMEM>>>(q, k, v, attn);

    // 5) expand router
    router_kernel<Rz, 1><<<Tz, 256>>>(attn, wro, nullptr, nullptr,
                                      wo, nullptr, nullptr, nullptr);

    // 6) A' = rnd(wo (x) attn)
    build_expand_A<<<Tz, 256>>>(attn, wo, P);

    // 7) out = A' @ expand_neurons
    tf32_gemm<<<dim3(Dz / 128, Tz / 128, 1), 256, GEMM_SMEM_TOTAL>>>(
        P, ENt, out, PCOLS, PCOLS, PCOLS, Dz, 0, 0);
}

// round 14
// speedup vs baseline: 1.5933x; 1.0194x over previous
#include <cuda_runtime.h>
#include <cstdint>

// ---------------------------------------------------------------------------
// NeuronCircuit: compress (MoE-weighted proj) -> causal MHA -> expand
// B=4 S=2048 D=1024 R=512 H=8 NC=NE=8 DH=64
//
// Round 13 -> 14 (small-kernel bundle; gemm/attention untouched):
//  * expand router + build_expand_A fused into one kernel (one attn pass).
//  * reduce_qkv vectorized to float4 (same per-element accumulation order).
// ---------------------------------------------------------------------------

#define Bz 4
#define Sz 2048
#define Dz 1024
#define Rz 512
#define Hz 8
#define NCz 8
#define DHz 64
#define Tz (Bz * Sz)          // 8192 tokens
#define PCOLS (NCz * Rz)      // 4096

// Scratch (device globals: allocation-free rule)
__device__ float g_P[(size_t)Tz * PCOLS];   // 134 MB, reused as A' for expand
__device__ float g_Xr[(size_t)Tz * Dz];     // tf32-rounded x (32 MB)
__device__ float g_q[Tz * Rz];
__device__ float g_k[Tz * Rz];
__device__ float g_v[Tz * Rz];
__device__ float g_attn[Tz * Rz];
__device__ float g_wq[Tz * NCz];
__device__ float g_wk[Tz * NCz];
__device__ float g_wv[Tz * NCz];
__device__ float g_CNt[(size_t)NCz * Rz * Dz];   // [NC][R][D]  (16 MB)
__device__ float g_ENt[(size_t)Dz * PCOLS];      // [D][NE*R]   (16 MB)

// ---------------------------------------------------------------------------
// Baseline-PTX helpers (valid on compute_103)
// ---------------------------------------------------------------------------
#define SW128(off) ((off) ^ (((off) >> 3) & 0x70))

__device__ __forceinline__ void cp_async16(void* smem_dst, const void* gmem_src) {
    uint32_t d = (uint32_t)__cvta_generic_to_shared(smem_dst);
    asm volatile("cp.async.cg.shared.global [%0], [%1], 16;"
                 :: "r"(d), "l"(gmem_src) : "memory");
}
#define CP_COMMIT() asm volatile("cp.async.commit_group;" ::: "memory")
#define CP_WAIT(n)  asm volatile("cp.async.wait_group %0;" :: "n"(n) : "memory")

__device__ __forceinline__ float tf32r(float x) {
    uint32_t r;
    asm("cvt.rna.tf32.f32 %0, %1;" : "=r"(r) : "f"(x));
    return __uint_as_float(r);
}

__device__ __forceinline__ void mma_tf32(float* d, const uint32_t* a, const uint32_t* b) {
    asm volatile(
        "mma.sync.aligned.m16n8k8.row.col.f32.tf32.tf32.f32 "
        "{%0,%1,%2,%3}, {%4,%5,%6,%7}, {%8,%9}, {%0,%1,%2,%3};"
        : "+f"(d[0]), "+f"(d[1]), "+f"(d[2]), "+f"(d[3])
        : "r"(a[0]), "r"(a[1]), "r"(a[2]), "r"(a[3]), "r"(b[0]), "r"(b[1]));
}

__device__ __forceinline__ void ldsm4(uint32_t (&r)[4], uint32_t addr) {
    asm volatile("ldmatrix.sync.aligned.m8n8.x4.shared.b16 {%0,%1,%2,%3}, [%4];"
                 : "=r"(r[0]), "=r"(r[1]), "=r"(r[2]), "=r"(r[3]) : "r"(addr));
}

// FFMA-only 2^y (y <= 0 after softmax-max subtraction), err ~2e-6
__device__ __forceinline__ float fexp2(float y) {
    y = fmaxf(y, -120.f);
    float tt = y + 12582912.f;                       // 1.5 * 2^23
    int i = __float_as_int(tt) - 0x4B400000;         // round(y)
    float f = y - (tt - 12582912.f);                 // frac in [-0.5, 0.5]
    float p =               1.3333558146428443e-3f;
    p = fmaf(p, f, 9.618129107628477e-3f);
    p = fmaf(p, f, 5.550410866482158e-2f);
    p = fmaf(p, f, 2.402265069591007e-1f);
    p = fmaf(p, f, 6.931471805599453e-1f);
    p = fmaf(p, f, 1.0f);
    return __int_as_float(__float_as_int(p) + (i << 23));
}

// ---------------------------------------------------------------------------
// Weight transpose (emits tf32-rounded values): out[c][r] = rnd(in[r][c])
// ---------------------------------------------------------------------------
__global__ __launch_bounds__(256) void transpose_kernel(
    const float* __restrict__ in, float* __restrict__ out,
    int rows, int cols, long zStride)
{
    __shared__ float tile[32][33];
    in  += (long)blockIdx.z * zStride;
    out += (long)blockIdx.z * zStride;
    const int c0 = blockIdx.x * 32;
    const int r0 = blockIdx.y * 32;
    const int tx = threadIdx.x & 31;
    const int ty = threadIdx.x >> 5;          // 0..7
#pragma unroll
    for (int j = 0; j < 32; j += 8)
        tile[ty + j][tx] = in[(long)(r0 + ty + j) * cols + c0 + tx];
    __syncthreads();
#pragma unroll
    for (int j = 0; j < 32; j += 8)
        out[(long)(c0 + ty + j) * rows + r0 + tx] = tf32r(tile[tx][ty + j]);
}

// ---------------------------------------------------------------------------
// tf32 mma.sync GEMM — 2-stage cp.async, ldmatrix, SW128 (unchanged).
// ---------------------------------------------------------------------------
#define GEMM_SMEM_TOTAL (2 * 32768)

__global__ __launch_bounds__(256) void tf32_gemm(
    const float* __restrict__ A, const float* __restrict__ Bt,
    float* __restrict__ C, int K, int lda, int ldb, int ldc,
    long bStride, long cStride)
{
    extern __shared__ __align__(1024) char smem[];
    const int tid = threadIdx.x;
    const int wid = tid >> 5;
    const int lane = tid & 31;
    const int g = lane >> 2;
    const int t = lane & 3;
    const int warp_m = wid >> 2;
    const int warp_n = wid & 3;

    Bt += (long)blockIdx.z * bStride;
    C  += (long)blockIdx.z * cStride;
    const int brow = blockIdx.y * 128;
    const int bcol = blockIdx.x * 128;

    const float* Ab = A + (long)brow * lda;
    const float* Bb = Bt + (long)bcol * ldb;

    const int lrow = tid >> 1;
    const int lch4 = (tid & 1) << 2;
    auto load_chunk = [&](int k0, int s) {
        char* sA = smem + s * 32768;
        char* sB = sA + 16384;
        const float* ga = Ab + (long)lrow * lda + k0 + (lch4 << 2);
        const float* gb = Bb + (long)lrow * ldb + k0 + (lch4 << 2);
#pragma unroll
        for (int c = 0; c < 4; c++) {
            const uint32_t off = SW128((uint32_t)((lrow << 7) + ((lch4 + c) << 4)));
            cp_async16(sA + off, ga + (c << 2));
            cp_async16(sB + off, gb + (c << 2));
        }
    };

    const int rowA = (((lane >> 3) & 1) << 3) + (lane & 7);
    const int colA = (lane >> 4) & 1;
    const int rowB = (((lane >> 4) & 1) << 3) + (lane & 7);
    const int colB = (lane >> 3) & 1;
    const uint32_t smem32 = (uint32_t)__cvta_generic_to_shared(smem);
    const uint32_t cAx = (uint32_t)(((colA << 4) ^ ((lane & 7) << 4)));
    const uint32_t cBx = (uint32_t)(((colB << 4) ^ ((lane & 7) << 4)));
    uint32_t aBase[4], bBase[2];
#pragma unroll
    for (int mt = 0; mt < 4; mt++)
        aBase[mt] = (uint32_t)((warp_m * 64 + mt * 16 + rowA) << 7);
#pragma unroll
    for (int np = 0; np < 2; np++)
        bBase[np] = (uint32_t)((warp_n * 32 + np * 16 + rowB) << 7) + 16384u;

    auto frag_ldsm = [&](uint32_t stage32, int ks,
                         uint32_t (&af)[4][4], uint32_t (&bf)[2][4]) {
        const uint32_t col = (uint32_t)(ks << 5);
#pragma unroll
        for (int mt = 0; mt < 4; mt++)
            ldsm4(af[mt], stage32 + aBase[mt] + (col ^ cAx));
#pragma unroll
        for (int np = 0; np < 2; np++)
            ldsm4(bf[np], stage32 + bBase[np] + (col ^ cBx));
    };

    float acc[4][4][4];
#pragma unroll
    for (int i = 0; i < 4; i++)
#pragma unroll
        for (int j = 0; j < 4; j++)
#pragma unroll
            for (int r = 0; r < 4; r++) acc[i][j][r] = 0.f;

    const int NCH = K >> 5;
    load_chunk(0, 0);
    CP_COMMIT();

    for (int i = 0; i < NCH; i++) {
        if (i + 1 < NCH) {
            load_chunk((i + 1) << 5, (i + 1) & 1);
            CP_COMMIT();
            CP_WAIT(1);
        } else {
            CP_WAIT(0);
        }
        __syncthreads();

        const uint32_t stage32 = smem32 + (uint32_t)((i & 1) * 32768);

        uint32_t af[2][4][4];
        uint32_t bf[2][2][4];
        frag_ldsm(stage32, 0, af[0], bf[0]);
#pragma unroll
        for (int ks = 0; ks < 4; ks++) {
            if (ks < 3) frag_ldsm(stage32, ks + 1, af[(ks + 1) & 1], bf[(ks + 1) & 1]);
            const int cur = ks & 1;
#pragma unroll
            for (int mt = 0; mt < 4; mt++)
#pragma unroll
                for (int nt = 0; nt < 4; nt++)
                    mma_tf32(acc[mt][nt], af[cur][mt],
                             &bf[cur][nt >> 1][(nt & 1) << 1]);
        }
        __syncthreads();
    }

#pragma unroll
    for (int mt = 0; mt < 4; mt++) {
        const int row = brow + warp_m * 64 + mt * 16 + g;
#pragma unroll
        for (int nt = 0; nt < 4; nt++) {
            const int col = bcol + warp_n * 32 + nt * 8 + 2 * t;
            float* Cp = C + (long)row * ldc + col;
            *(float2*)Cp = make_float2(acc[mt][nt][0], acc[mt][nt][1]);
            *(float2*)(Cp + 8 * ldc) = make_float2(acc[mt][nt][2], acc[mt][nt][3]);
        }
    }
}

// ---------------------------------------------------------------------------
// Compress router (3 routers), also emits tf32-rounded x
// ---------------------------------------------------------------------------
template <int DIM, int NR>
__global__ __launch_bounds__(256) void router_kernel(
    const float* __restrict__ x,
    const float* __restrict__ wr0, const float* __restrict__ wr1,
    const float* __restrict__ wr2,
    float* __restrict__ o0, float* __restrict__ o1, float* __restrict__ o2,
    float* __restrict__ xrOut)
{
    __shared__ float xs[DIM];
    __shared__ float lg[NR][8];
    const long t = blockIdx.x;
    const float4* xrow = (const float4*)(x + t * DIM);
    for (int i = threadIdx.x; i < DIM / 4; i += 256)
        ((float4*)xs)[i] = xrow[i];
    __syncthreads();

    if (xrOut) {
        float4* xo = (float4*)(xrOut + t * DIM);
        for (int i = threadIdx.x; i < DIM / 4; i += 256) {
            float4 v = ((const float4*)xs)[i];
            xo[i] = make_float4(tf32r(v.x), tf32r(v.y), tf32r(v.z), tf32r(v.w));
        }
    }

    const int w = threadIdx.x >> 5;
    const int lane = threadIdx.x & 31;
    const float* wrs[3] = {wr0, wr1, wr2};
#pragma unroll
    for (int rt = 0; rt < NR; rt++) {
        const float4* wv4 = (const float4*)(wrs[rt] + w * DIM);
        float s = 0.f;
#pragma unroll
        for (int i = lane; i < DIM / 4; i += 32) {
            float4 a = ((const float4*)xs)[i];
            float4 b = wv4[i];
            s += a.x * b.x + a.y * b.y + a.z * b.z + a.w * b.w;
        }
#pragma unroll
        for (int off = 16; off; off >>= 1)
            s += __shfl_xor_sync(0xffffffffu, s, off);
        if (lane == 0) lg[rt][w] = s;
    }
    __syncthreads();

    if (threadIdx.x < NR) {
        const int rt = threadIdx.x;
        float mx = lg[rt][0];
#pragma unroll
        for (int n = 1; n < 8; n++) mx = fmaxf(mx, lg[rt][n]);
        float e[8];
        float sum = 0.f;
#pragma unroll
        for (int n = 0; n < 8; n++) { e[n] = __expf(lg[rt][n] - mx); sum += e[n]; }
        const float inv = 1.f / sum;
        float* o = (rt == 0 ? o0 : (rt == 1 ? o1 : o2)) + t * 8;
#pragma unroll
        for (int n = 0; n < 8; n++) o[n] = e[n] * inv;
    }
}

// ---------------------------------------------------------------------------
// FUSED expand router + A' build:
//   ws = softmax(attn[t] . wro)  (identical arithmetic to router_kernel)
//   A'[t, n*512+r] = tf32r(ws[n] * attn[t,r])
// One pass over attn per token; no separate wo buffer.
// ---------------------------------------------------------------------------
__global__ __launch_bounds__(256) void router_expand_fused(
    const float* __restrict__ attn, const float* __restrict__ wro,
    float* __restrict__ Aout)
{
    __shared__ float xs[Rz];
    __shared__ float lg[8];
    __shared__ float ws[8];
    const long t = blockIdx.x;
    for (int i = threadIdx.x; i < Rz / 4; i += 256)
        ((float4*)xs)[i] = ((const float4*)(attn + t * Rz))[i];
    __syncthreads();

    const int w = threadIdx.x >> 5;
    const int lane = threadIdx.x & 31;
    {
        const float4* wv4 = (const float4*)(wro + w * Rz);
        float s = 0.f;
#pragma unroll
        for (int i = lane; i < Rz / 4; i += 32) {
            float4 a = ((const float4*)xs)[i];
            float4 b = wv4[i];
            s += a.x * b.x + a.y * b.y + a.z * b.z + a.w * b.w;
        }
#pragma unroll
        for (int off = 16; off; off >>= 1)
            s += __shfl_xor_sync(0xffffffffu, s, off);
        if (lane == 0) lg[w] = s;
    }
    __syncthreads();

    if (threadIdx.x == 0) {
        float mx = lg[0];
#pragma unroll
        for (int n = 1; n < 8; n++) mx = fmaxf(mx, lg[n]);
        float e[8];
        float sum = 0.f;
#pragma unroll
        for (int n = 0; n < 8; n++) { e[n] = __expf(lg[n] - mx); sum += e[n]; }
        const float inv = 1.f / sum;
#pragma unroll
        for (int n = 0; n < 8; n++) ws[n] = e[n] * inv;
    }
    __syncthreads();

    for (int i = threadIdx.x; i < (8 * Rz / 4); i += 256) {
        const int n = i >> 7;
        const int r4 = i & 127;
        float4 a = ((float4*)xs)[r4];
        const float wn = ws[n];
        ((float4*)(Aout + t * PCOLS + n * Rz))[r4] =
            make_float4(tf32r(a.x * wn), tf32r(a.y * wn),
                        tf32r(a.z * wn), tf32r(a.w * wn));
    }
}

// ---------------------------------------------------------------------------
// q/k/v[t,r] = tf32rnd( sum_n P[t, n*512 + r] * w{q,k,v}[t,n] )
// float4 per thread (128 threads x 4 r = 512); same per-element sum order.
// ---------------------------------------------------------------------------
__global__ __launch_bounds__(128) void reduce_qkv(
    const float* __restrict__ P,
    const float* __restrict__ wq, const float* __restrict__ wk,
    const float* __restrict__ wv,
    float* __restrict__ q, float* __restrict__ k, float* __restrict__ v)
{
    const long t = blockIdx.x;
    __shared__ float sq[8], sk[8], sv[8];
    if (threadIdx.x < 8) {
        sq[threadIdx.x] = wq[t * 8 + threadIdx.x];
        sk[threadIdx.x] = wk[t * 8 + threadIdx.x];
        sv[threadIdx.x] = wv[t * 8 + threadIdx.x];
    }
    __syncthreads();
    const float* Pt = P + t * PCOLS;
    const int r4 = threadIdx.x;                 // float4 index 0..127
    float4 aq = make_float4(0.f, 0.f, 0.f, 0.f);
    float4 ak = aq, av = aq;
#pragma unroll
    for (int n = 0; n < 8; n++) {
        const float4 p = ((const float4*)(Pt + n * Rz))[r4];
        const float cq = sq[n], ck = sk[n], cv = sv[n];
        aq.x += p.x * cq; aq.y += p.y * cq; aq.z += p.z * cq; aq.w += p.w * cq;
        ak.x += p.x * ck; ak.y += p.y * ck; ak.z += p.z * ck; ak.w += p.w * ck;
        av.x += p.x * cv; av.y += p.y * cv; av.z += p.z * cv; av.w += p.w * cv;
    }
    ((float4*)(q + t * Rz))[r4] =
        make_float4(tf32r(aq.x), tf32r(aq.y), tf32r(aq.z), tf32r(aq.w));
    ((float4*)(k + t * Rz))[r4] =
        make_float4(tf32r(ak.x), tf32r(ak.y), tf32r(ak.z), tf32r(ak.w));
    ((float4*)(v + t * Rz))[r4] =
        make_float4(tf32r(av.x), tf32r(av.y), tf32r(av.z), tf32r(av.w));
}

// ---------------------------------------------------------------------------
// Tensor-core causal flash attention (tf32 mma.sync), q/k/v pre-rounded.
// K/V tiles double-buffered with cp.async (unchanged from R13).
// ---------------------------------------------------------------------------
#define PADT 68
#define KVSTAGE (2 * 64 * PADT)              // floats per stage (Ks+Vn)
#define ATTN_SMEM ((2 * KVSTAGE + 64 * PADT) * 4)
#define SCALE_L2E 0.1803368801111204f        // (1/sqrt(64)) * log2(e)

__global__ __launch_bounds__(128) void attn_tc_kernel(
    const float* __restrict__ q, const float* __restrict__ k,
    const float* __restrict__ v, float* __restrict__ out)
{
    extern __shared__ __align__(16) float sm[];
    float* Ps = sm + 2 * KVSTAGE;      // [64][PADT], warp w owns rows w*16..+15

    const int bh = blockIdx.y;
    const int b = bh >> 3;
    const int h = bh & 7;
    const int qblk = gridDim.x - 1 - blockIdx.x;   // long blocks first
    const int qbase = qblk * 64;
    const int tid = threadIdx.x;
    const int w = tid >> 5;
    const int lane = tid & 31;
    const int g = lane >> 2;
    const int t = lane & 3;

    // Q fragments (already tf32-rounded)
    const float* qb = q + ((long)b * Sz + qbase + w * 16) * Rz + h * DHz;
    uint32_t qf[8][4];
#pragma unroll
    for (int ks = 0; ks < 8; ks++) {
        qf[ks][0] = __float_as_uint(qb[(long)g * Rz + 8 * ks + t]);
        qf[ks][1] = __float_as_uint(qb[(long)(g + 8) * Rz + 8 * ks + t]);
        qf[ks][2] = __float_as_uint(qb[(long)g * Rz + 8 * ks + t + 4]);
        qf[ks][3] = __float_as_uint(qb[(long)(g + 8) * Rz + 8 * ks + t + 4]);
    }

    float Oa[4][2][4];                  // [d-mtile][q-nfrag][regs], transposed
#pragma unroll
    for (int a = 0; a < 4; a++)
#pragma unroll
        for (int bb = 0; bb < 2; bb++)
#pragma unroll
            for (int c = 0; c < 4; c++) Oa[a][bb][c] = 0.f;
    float m_lo = -1e30f, m_hi = -1e30f, l_lo = 0.f, l_hi = 0.f;

    const float* kb = k + (long)b * Sz * Rz + h * DHz;
    const float* vb = v + (long)b * Sz * Rz + h * DHz;
    const int ntiles = qblk + 1;

    auto loadKV = [&](int tile, int s) {
        float* Kd = sm + s * KVSTAGE;
        float* Vd = Kd + 64 * PADT;
        const long base = (long)(tile * 64);
#pragma unroll
        for (int i = tid; i < 1024; i += 128) {
            const int row = i >> 4;
            const int col = (i & 15) << 2;
            cp_async16(Kd + row * PADT + col, kb + (base + row) * Rz + col);
            cp_async16(Vd + row * PADT + col, vb + (base + row) * Rz + col);
        }
    };

    loadKV(0, 0);
    CP_COMMIT();

    for (int tt = 0; tt < ntiles; tt++) {
        const int s = tt & 1;
        CP_WAIT(0);
        __syncthreads();
        if (tt + 1 < ntiles) {
            loadKV(tt + 1, s ^ 1);
            CP_COMMIT();
        }
        const float* Ks = sm + s * KVSTAGE;
        const float* Vn = Ks + 64 * PADT;

        // S = Q @ K^T
        float S[8][4];
#pragma unroll
        for (int nf = 0; nf < 8; nf++)
#pragma unroll
            for (int c = 0; c < 4; c++) S[nf][c] = 0.f;
#pragma unroll
        for (int ks = 0; ks < 8; ks++) {
            const int c0 = 8 * ks + t, c1 = c0 + 4;
#pragma unroll
            for (int nf = 0; nf < 8; nf++) {
                uint32_t bfr[2];
                bfr[0] = __float_as_uint(Ks[(nf * 8 + g) * PADT + c0]);
                bfr[1] = __float_as_uint(Ks[(nf * 8 + g) * PADT + c1]);
                mma_tf32(S[nf], qf[ks], bfr);
            }
        }

        if (tt == qblk) {
            const int rl = w * 16 + g, rh = rl + 8;
#pragma unroll
            for (int nf = 0; nf < 8; nf++) {
                const int c0 = nf * 8 + 2 * t;
                if (c0 > rl)     S[nf][0] = -1e30f;
                if (c0 + 1 > rl) S[nf][1] = -1e30f;
                if (c0 > rh)     S[nf][2] = -1e30f;
                if (c0 + 1 > rh) S[nf][3] = -1e30f;
            }
        }

        float mx_lo = -1e30f, mx_hi = -1e30f;
#pragma unroll
        for (int nf = 0; nf < 8; nf++) {
            mx_lo = fmaxf(mx_lo, fmaxf(S[nf][0], S[nf][1]));
            mx_hi = fmaxf(mx_hi, fmaxf(S[nf][2], S[nf][3]));
        }
        mx_lo = fmaxf(mx_lo, __shfl_xor_sync(0xffffffffu, mx_lo, 1));
        mx_lo = fmaxf(mx_lo, __shfl_xor_sync(0xffffffffu, mx_lo, 2));
        mx_hi = fmaxf(mx_hi, __shfl_xor_sync(0xffffffffu, mx_hi, 1));
        mx_hi = fmaxf(mx_hi, __shfl_xor_sync(0xffffffffu, mx_hi, 2));

        const float mn_lo = fmaxf(m_lo, mx_lo);
        const float mn_hi = fmaxf(m_hi, mx_hi);
        const float corr_lo = fexp2((m_lo - mn_lo) * SCALE_L2E);
        const float corr_hi = fexp2((m_hi - mn_hi) * SCALE_L2E);
        m_lo = mn_lo; m_hi = mn_hi;
        l_lo *= corr_lo; l_hi *= corr_hi;

        float psum_lo = 0.f, psum_hi = 0.f;
        float* pw = Ps + (w * 16) * PADT;
#pragma unroll
        for (int nf = 0; nf < 8; nf++) {
            const int c0 = nf * 8 + 2 * t;
            float p0 = fexp2((S[nf][0] - mn_lo) * SCALE_L2E);
            float p1 = fexp2((S[nf][1] - mn_lo) * SCALE_L2E);
            float p2 = fexp2((S[nf][2] - mn_hi) * SCALE_L2E);
            float p3 = fexp2((S[nf][3] - mn_hi) * SCALE_L2E);
            psum_lo += p0 + p1;
            psum_hi += p2 + p3;
            *(float2*)(pw + g * PADT + c0) = make_float2(tf32r(p0), tf32r(p1));
            *(float2*)(pw + (g + 8) * PADT + c0) = make_float2(tf32r(p2), tf32r(p3));
        }
        psum_lo += __shfl_xor_sync(0xffffffffu, psum_lo, 1);
        psum_lo += __shfl_xor_sync(0xffffffffu, psum_lo, 2);
        psum_hi += __shfl_xor_sync(0xffffffffu, psum_hi, 1);
        psum_hi += __shfl_xor_sync(0xffffffffu, psum_hi, 2);
        l_lo += psum_lo; l_hi += psum_hi;

        {
            const float cA  = __shfl_sync(0xffffffffu, corr_lo, 8 * t);
            const float cA1 = __shfl_sync(0xffffffffu, corr_lo, 8 * t + 4);
            const float cB  = __shfl_sync(0xffffffffu, corr_hi, 8 * t);
            const float cB1 = __shfl_sync(0xffffffffu, corr_hi, 8 * t + 4);
#pragma unroll
            for (int mt = 0; mt < 4; mt++) {
                Oa[mt][0][0] *= cA;  Oa[mt][0][1] *= cA1;
                Oa[mt][0][2] *= cA;  Oa[mt][0][3] *= cA1;
                Oa[mt][1][0] *= cB;  Oa[mt][1][1] *= cB1;
                Oa[mt][1][2] *= cB;  Oa[mt][1][3] *= cB1;
            }
        }
        __syncwarp();

#pragma unroll
        for (int ks = 0; ks < 8; ks++) {
            const int k0 = 8 * ks + t, k1 = k0 + 4;
            uint32_t bfr[2][2];
#pragma unroll
            for (int nf2 = 0; nf2 < 2; nf2++) {
                bfr[nf2][0] = __float_as_uint(pw[(nf2 * 8 + g) * PADT + k0]);
                bfr[nf2][1] = __float_as_uint(pw[(nf2 * 8 + g) * PADT + k1]);
            }
#pragma unroll
            for (int mt = 0; mt < 4; mt++) {
                uint32_t af[4];
                af[0] = __float_as_uint(Vn[k0 * PADT + mt * 16 + g]);
                af[1] = __float_as_uint(Vn[k0 * PADT + mt * 16 + g + 8]);
                af[2] = __float_as_uint(Vn[k1 * PADT + mt * 16 + g]);
                af[3] = __float_as_uint(Vn[k1 * PADT + mt * 16 + g + 8]);
                mma_tf32(Oa[mt][0], af, bfr[0]);
                mma_tf32(Oa[mt][1], af, bfr[1]);
            }
        }
        __syncwarp();
    }

    const float il_lo = 1.f / l_lo;
    const float il_hi = 1.f / l_hi;
    {
        const float iA  = __shfl_sync(0xffffffffu, il_lo, 8 * t);
        const float iA1 = __shfl_sync(0xffffffffu, il_lo, 8 * t + 4);
        const float iB  = __shfl_sync(0xffffffffu, il_hi, 8 * t);
        const float iB1 = __shfl_sync(0xffffffffu, il_hi, 8 * t + 4);
#pragma unroll
        for (int mt = 0; mt < 4; mt++) {
            Oa[mt][0][0] *= iA;  Oa[mt][0][1] *= iA1;
            Oa[mt][0][2] *= iA;  Oa[mt][0][3] *= iA1;
            Oa[mt][1][0] *= iB;  Oa[mt][1][1] *= iB1;
            Oa[mt][1][2] *= iB;  Oa[mt][1][3] *= iB1;
        }
    }

    float* osm = Ps + (w * 16) * PADT;
    __syncwarp();
#pragma unroll
    for (int mt = 0; mt < 4; mt++) {
#pragma unroll
        for (int nf2 = 0; nf2 < 2; nf2++) {
            const int qc = nf2 * 8 + 2 * t;
            osm[(mt * 16 + g) * 17 + qc]         = Oa[mt][nf2][0];
            osm[(mt * 16 + g) * 17 + qc + 1]     = Oa[mt][nf2][1];
            osm[(mt * 16 + g + 8) * 17 + qc]     = Oa[mt][nf2][2];
            osm[(mt * 16 + g + 8) * 17 + qc + 1] = Oa[mt][nf2][3];
        }
    }
    __syncwarp();
    float* ob = out + ((long)b * Sz + qbase + w * 16) * Rz + h * DHz;
#pragma unroll
    for (int it = 0; it < 8; it++) {
        const int qr = it * 2 + (lane >> 4);
        const int d4 = (lane & 15) << 2;
        float4 vv;
        vv.x = osm[(d4 + 0) * 17 + qr];
        vv.y = osm[(d4 + 1) * 17 + qr];
        vv.z = osm[(d4 + 2) * 17 + qr];
        vv.w = osm[(d4 + 3) * 17 + qr];
        *(float4*)(ob + (long)qr * Rz + d4) = vv;
    }
}

// ---------------------------------------------------------------------------
extern "C" void kernel_launch(void* const* d_in, const int* in_sizes, int n_in,
                              void* d_out, int out_size)
{
    const float* x   = (const float*)d_in[0];
    // d_in[1] = mask: always causal tril -> applied analytically, not read
    const float* CN  = (const float*)d_in[2];  // [NC, D, R]
    const float* EN  = (const float*)d_in[3];  // [NE, R, D]
    const float* wrq = (const float*)d_in[4];
    const float* wrk = (const float*)d_in[5];
    const float* wrv = (const float*)d_in[6];
    const float* wro = (const float*)d_in[7];
    float* out = (float*)d_out;

    float *P, *Xr, *q, *k, *v, *attn, *wq, *wk, *wv, *CNt, *ENt;
    cudaGetSymbolAddress((void**)&P,    g_P);
    cudaGetSymbolAddress((void**)&Xr,   g_Xr);
    cudaGetSymbolAddress((void**)&q,    g_q);
    cudaGetSymbolAddress((void**)&k,    g_k);
    cudaGetSymbolAddress((void**)&v,    g_v);
    cudaGetSymbolAddress((void**)&attn, g_attn);
    cudaGetSymbolAddress((void**)&wq,   g_wq);
    cudaGetSymbolAddress((void**)&wk,   g_wk);
    cudaGetSymbolAddress((void**)&wv,   g_wv);
    cudaGetSymbolAddress((void**)&CNt,  g_CNt);
    cudaGetSymbolAddress((void**)&ENt,  g_ENt);

    cudaFuncSetAttribute(tf32_gemm,
                         cudaFuncAttributeMaxDynamicSharedMemorySize, GEMM_SMEM_TOTAL);
    cudaFuncSetAttribute(attn_tc_kernel,
                         cudaFuncAttributeMaxDynamicSharedMemorySize, ATTN_SMEM);

    // 0) pre-round weights (transposed)
    transpose_kernel<<<dim3(Rz / 32, Dz / 32, NCz), 256>>>(
        CN, CNt, Dz, Rz, (long)Dz * Rz);
    transpose_kernel<<<dim3(Dz / 32, PCOLS / 32, 1), 256>>>(
        EN, ENt, PCOLS, Dz, 0);

    // 1) compress routers (also emits tf32-rounded Xr)
    router_kernel<Dz, 3><<<Tz, 256>>>(x, wrq, wrk, wrv, wq, wk, wv, Xr);

    // 2) P = x @ compress_neurons
    tf32_gemm<<<dim3(Rz / 128, Tz / 128, NCz), 256, GEMM_SMEM_TOTAL>>>(
        Xr, CNt, P, Dz, Dz, Dz, PCOLS, (long)Rz * Dz, (long)Rz);

    // 3) weighted reduce -> q,k,v (tf32-rounded, float4)
    reduce_qkv<<<Tz, 128>>>(P, wq, wk, wv, q, k, v);

    // 4) causal attention (tensor cores, cp.async K/V pipeline)
    attn_tc_kernel<<<dim3(Sz / 64, Bz * Hz), 128, ATTN_SMEM>>>(q, k, v, attn);

    // 5+6) fused expand router + A' build (one attn pass)
    router_expand_fused<<<Tz, 256>>>(attn, wro, P);

    // 7) out = A' @ expand_neurons
    tf32_gemm<<<dim3(Dz / 128, Tz / 128, 1), 256, GEMM_SMEM_TOTAL>>>(
        P, ENt, out, PCOLS, PCOLS, PCOLS, Dz, 0, 0);
}

// round 16
// speedup vs baseline: 2.4911x; 1.5635x over previous
#include <cuda_runtime.h>
#include <cuda_fp16.h>
#include <cstdint>

// ---------------------------------------------------------------------------
// NeuronCircuit: compress (MoE-weighted proj) -> causal MHA -> expand
// B=4 S=2048 D=1024 R=512 H=8 NC=NE=8 DH=64
//
// Round 14 -> 15: GEMMs switched from tf32 (m16n8k8) to fp16 (m16n8k16),
// fp32 accumulate. Same 10-bit mantissa as tf32; 2x K-work per mma and half
// the smem bytes per FLOP. BK=64 halves (128B rows) keeps the SW128/ldmatrix
// addressing code identical. Operand converters emit __half. Attention,
// reduce_qkv, P and q/k/v unchanged from R14.
// ---------------------------------------------------------------------------

#define Bz 4
#define Sz 2048
#define Dz 1024
#define Rz 512
#define Hz 8
#define NCz 8
#define DHz 64
#define Tz (Bz * Sz)          // 8192 tokens
#define PCOLS (NCz * Rz)      // 4096

// Scratch (device globals: allocation-free rule)
__device__ float  g_P[(size_t)Tz * PCOLS];     // 134 MB (gemm1 output, fp32)
__device__ __half g_Xh[(size_t)Tz * Dz];       // fp16 x (16 MB)
__device__ __half g_Ah[(size_t)Tz * PCOLS];    // fp16 A' (67 MB)
__device__ float  g_q[Tz * Rz];
__device__ float  g_k[Tz * Rz];
__device__ float  g_v[Tz * Rz];
__device__ float  g_attn[Tz * Rz];
__device__ float  g_wq[Tz * NCz];
__device__ float  g_wk[Tz * NCz];
__device__ float  g_wv[Tz * NCz];
__device__ __half g_CNh[(size_t)NCz * Rz * Dz];  // [NC][R][D] fp16 (8 MB)
__device__ __half g_ENh[(size_t)Dz * PCOLS];     // [D][NE*R]  fp16 (8 MB)

// ---------------------------------------------------------------------------
// Baseline-PTX helpers (valid on compute_103)
// ---------------------------------------------------------------------------
#define SW128(off) ((off) ^ (((off) >> 3) & 0x70))

__device__ __forceinline__ void cp_async16(void* smem_dst, const void* gmem_src) {
    uint32_t d = (uint32_t)__cvta_generic_to_shared(smem_dst);
    asm volatile("cp.async.cg.shared.global [%0], [%1], 16;"
                 :: "r"(d), "l"(gmem_src) : "memory");
}
#define CP_COMMIT() asm volatile("cp.async.commit_group;" ::: "memory")
#define CP_WAIT(n)  asm volatile("cp.async.wait_group %0;" :: "n"(n) : "memory")

__device__ __forceinline__ float tf32r(float x) {
    uint32_t r;
    asm("cvt.rna.tf32.f32 %0, %1;" : "=r"(r) : "f"(x));
    return __uint_as_float(r);
}

__device__ __forceinline__ void mma_tf32(float* d, const uint32_t* a, const uint32_t* b) {
    asm volatile(
        "mma.sync.aligned.m16n8k8.row.col.f32.tf32.tf32.f32 "
        "{%0,%1,%2,%3}, {%4,%5,%6,%7}, {%8,%9}, {%0,%1,%2,%3};"
        : "+f"(d[0]), "+f"(d[1]), "+f"(d[2]), "+f"(d[3])
        : "r"(a[0]), "r"(a[1]), "r"(a[2]), "r"(a[3]), "r"(b[0]), "r"(b[1]));
}

__device__ __forceinline__ void mma_f16(float* d, const uint32_t* a, const uint32_t* b) {
    asm volatile(
        "mma.sync.aligned.m16n8k16.row.col.f32.f16.f16.f32 "
        "{%0,%1,%2,%3}, {%4,%5,%6,%7}, {%8,%9}, {%0,%1,%2,%3};"
        : "+f"(d[0]), "+f"(d[1]), "+f"(d[2]), "+f"(d[3])
        : "r"(a[0]), "r"(a[1]), "r"(a[2]), "r"(a[3]), "r"(b[0]), "r"(b[1]));
}

__device__ __forceinline__ void ldsm4(uint32_t (&r)[4], uint32_t addr) {
    asm volatile("ldmatrix.sync.aligned.m8n8.x4.shared.b16 {%0,%1,%2,%3}, [%4];"
                 : "=r"(r[0]), "=r"(r[1]), "=r"(r[2]), "=r"(r[3]) : "r"(addr));
}

// FFMA-only 2^y (y <= 0 after softmax-max subtraction), err ~2e-6
__device__ __forceinline__ float fexp2(float y) {
    y = fmaxf(y, -120.f);
    float tt = y + 12582912.f;                       // 1.5 * 2^23
    int i = __float_as_int(tt) - 0x4B400000;         // round(y)
    float f = y - (tt - 12582912.f);                 // frac in [-0.5, 0.5]
    float p =               1.3333558146428443e-3f;
    p = fmaf(p, f, 9.618129107628477e-3f);
    p = fmaf(p, f, 5.550410866482158e-2f);
    p = fmaf(p, f, 2.402265069591007e-1f);
    p = fmaf(p, f, 6.931471805599453e-1f);
    p = fmaf(p, f, 1.0f);
    return __int_as_float(__float_as_int(p) + (i << 23));
}

// ---------------------------------------------------------------------------
// Weight transpose, fp16 output: out[c][r] = half(in[r][c])
// ---------------------------------------------------------------------------
__global__ __launch_bounds__(256) void transpose_h_kernel(
    const float* __restrict__ in, __half* __restrict__ out,
    int rows, int cols, long zStrideIn, long zStrideOut)
{
    __shared__ float tile[32][33];
    in  += (long)blockIdx.z * zStrideIn;
    out += (long)blockIdx.z * zStrideOut;
    const int c0 = blockIdx.x * 32;
    const int r0 = blockIdx.y * 32;
    const int tx = threadIdx.x & 31;
    const int ty = threadIdx.x >> 5;          // 0..7
#pragma unroll
    for (int j = 0; j < 32; j += 8)
        tile[ty + j][tx] = in[(long)(r0 + ty + j) * cols + c0 + tx];
    __syncthreads();
#pragma unroll
    for (int j = 0; j < 32; j += 8)
        out[(long)(c0 + ty + j) * rows + r0 + tx] = __float2half_rn(tile[tx][ty + j]);
}

// ---------------------------------------------------------------------------
// fp16 mma.sync GEMM: C[M,N](f32) = A[M,K](f16 row-major) x Bt[N,K](f16
// K-major rows). CTA 128x128, BK=64 halves (128B rows, SW128), 8 warps
// (warp tile 64x32), 2-stage cp.async, ldmatrix fragments.
// ---------------------------------------------------------------------------
#define GEMM_SMEM_TOTAL (2 * 32768)

__global__ __launch_bounds__(256) void h_gemm(
    const __half* __restrict__ A, const __half* __restrict__ Bt,
    float* __restrict__ C, int K, int lda, int ldb, int ldc,
    long bStride, long cStride)
{
    extern __shared__ __align__(1024) char smem[];
    const int tid = threadIdx.x;
    const int wid = tid >> 5;
    const int lane = tid & 31;
    const int g = lane >> 2;
    const int t = lane & 3;
    const int warp_m = wid >> 2;
    const int warp_n = wid & 3;

    Bt += (long)blockIdx.z * bStride;
    C  += (long)blockIdx.z * cStride;
    const int brow = blockIdx.y * 128;
    const int bcol = blockIdx.x * 128;

    const __half* Ab = A + (long)brow * lda;
    const __half* Bb = Bt + (long)bcol * ldb;

    // loader: 128 rows x 64 halves (=128B) per matrix; 2 threads/row, 4x16B each
    const int lrow = tid >> 1;
    const int lch = (tid & 1) << 2;           // chunk 0 or 4 (16B chunks)
    auto load_chunk = [&](int k0, int s) {
        char* sA = smem + s * 32768;
        char* sB = sA + 16384;
        const __half* ga = Ab + (long)lrow * lda + k0 + (lch << 3);
        const __half* gb = Bb + (long)lrow * ldb + k0 + (lch << 3);
#pragma unroll
        for (int c = 0; c < 4; c++) {
            const uint32_t off = SW128((uint32_t)((lrow << 7) + ((lch + c) << 4)));
            cp_async16(sA + off, ga + (c << 3));
            cp_async16(sB + off, gb + (c << 3));
        }
    };

    // ldmatrix lane geometry (identical byte layout to the tf32 version):
    //  A x4: m0=(r0-7,h0-7) m1=(r8-15,h0-7) m2=(r0-7,h8-15) m3=(r8-15,h8-15)
    //  B x4: m0=(n0-7,h0-7) m1=(n0-7,h8-15) m2=(n8-15,h0-7) m3=(n8-15,h8-15)
    const int rowA = (((lane >> 3) & 1) << 3) + (lane & 7);
    const int colA = (lane >> 4) & 1;
    const int rowB = (((lane >> 4) & 1) << 3) + (lane & 7);
    const int colB = (lane >> 3) & 1;
    const uint32_t smem32 = (uint32_t)__cvta_generic_to_shared(smem);
    const uint32_t cAx = (uint32_t)(((colA << 4) ^ ((lane & 7) << 4)));
    const uint32_t cBx = (uint32_t)(((colB << 4) ^ ((lane & 7) << 4)));
    uint32_t aBase[4], bBase[2];
#pragma unroll
    for (int mt = 0; mt < 4; mt++)
        aBase[mt] = (uint32_t)((warp_m * 64 + mt * 16 + rowA) << 7);
#pragma unroll
    for (int np = 0; np < 2; np++)
        bBase[np] = (uint32_t)((warp_n * 32 + np * 16 + rowB) << 7) + 16384u;

    auto frag_ldsm = [&](uint32_t stage32, int ks,
                         uint32_t (&af)[4][4], uint32_t (&bf)[2][4]) {
        const uint32_t col = (uint32_t)(ks << 5);        // 16 halves = 32B per kstep
#pragma unroll
        for (int mt = 0; mt < 4; mt++)
            ldsm4(af[mt], stage32 + aBase[mt] + (col ^ cAx));
#pragma unroll
        for (int np = 0; np < 2; np++)
            ldsm4(bf[np], stage32 + bBase[np] + (col ^ cBx));
    };

    float acc[4][4][4];
#pragma unroll
    for (int i = 0; i < 4; i++)
#pragma unroll
        for (int j = 0; j < 4; j++)
#pragma unroll
            for (int r = 0; r < 4; r++) acc[i][j][r] = 0.f;

    const int NCH = K >> 6;                   // BK = 64 halves
    load_chunk(0, 0);
    CP_COMMIT();

    for (int i = 0; i < NCH; i++) {
        if (i + 1 < NCH) {
            load_chunk((i + 1) << 6, (i + 1) & 1);
            CP_COMMIT();
            CP_WAIT(1);
        } else {
            CP_WAIT(0);
        }
        __syncthreads();

        const uint32_t stage32 = smem32 + (uint32_t)((i & 1) * 32768);

        uint32_t af[2][4][4];
        uint32_t bf[2][2][4];
        frag_ldsm(stage32, 0, af[0], bf[0]);
#pragma unroll
        for (int ks = 0; ks < 4; ks++) {      // 4 ksteps of k16
            if (ks < 3) frag_ldsm(stage32, ks + 1, af[(ks + 1) & 1], bf[(ks + 1) & 1]);
            const int cur = ks & 1;
#pragma unroll
            for (int mt = 0; mt < 4; mt++)
#pragma unroll
                for (int nt = 0; nt < 4; nt++)
                    mma_f16(acc[mt][nt], af[cur][mt],
                            &bf[cur][nt >> 1][(nt & 1) << 1]);
        }
        __syncthreads();
    }

    // epilogue: c0,c1 at (row, col+2t), c2,c3 at (row+8, col+2t)
#pragma unroll
    for (int mt = 0; mt < 4; mt++) {
        const int row = brow + warp_m * 64 + mt * 16 + g;
#pragma unroll
        for (int nt = 0; nt < 4; nt++) {
            const int col = bcol + warp_n * 32 + nt * 8 + 2 * t;
            float* Cp = C + (long)row * ldc + col;
            *(float2*)Cp = make_float2(acc[mt][nt][0], acc[mt][nt][1]);
            *(float2*)(Cp + 8 * ldc) = make_float2(acc[mt][nt][2], acc[mt][nt][3]);
        }
    }
}

// ---------------------------------------------------------------------------
// Compress router (3 routers), also emits fp16 x for gemm1
// ---------------------------------------------------------------------------
template <int DIM, int NR>
__global__ __launch_bounds__(256) void router_kernel(
    const float* __restrict__ x,
    const float* __restrict__ wr0, const float* __restrict__ wr1,
    const float* __restrict__ wr2,
    float* __restrict__ o0, float* __restrict__ o1, float* __restrict__ o2,
    __half* __restrict__ xhOut)
{
    __shared__ float xs[DIM];
    __shared__ float lg[NR][8];
    const long t = blockIdx.x;
    const float4* xrow = (const float4*)(x + t * DIM);
    for (int i = threadIdx.x; i < DIM / 4; i += 256)
        ((float4*)xs)[i] = xrow[i];
    __syncthreads();

    if (xhOut) {
        __half2* xo = (__half2*)(xhOut + t * DIM);
        for (int i = threadIdx.x; i < DIM / 4; i += 256) {
            float4 v = ((const float4*)xs)[i];
            xo[2 * i]     = __floats2half2_rn(v.x, v.y);
            xo[2 * i + 1] = __floats2half2_rn(v.z, v.w);
        }
    }

    const int w = threadIdx.x >> 5;
    const int lane = threadIdx.x & 31;
    const float* wrs[3] = {wr0, wr1, wr2};
#pragma unroll
    for (int rt = 0; rt < NR; rt++) {
        const float4* wv4 = (const float4*)(wrs[rt] + w * DIM);
        float s = 0.f;
#pragma unroll
        for (int i = lane; i < DIM / 4; i += 32) {
            float4 a = ((const float4*)xs)[i];
            float4 b = wv4[i];
            s += a.x * b.x + a.y * b.y + a.z * b.z + a.w * b.w;
        }
#pragma unroll
        for (int off = 16; off; off >>= 1)
            s += __shfl_xor_sync(0xffffffffu, s, off);
        if (lane == 0) lg[rt][w] = s;
    }
    __syncthreads();

    if (threadIdx.x < NR) {
        const int rt = threadIdx.x;
        float mx = lg[rt][0];
#pragma unroll
        for (int n = 1; n < 8; n++) mx = fmaxf(mx, lg[rt][n]);
        float e[8];
        float sum = 0.f;
#pragma unroll
        for (int n = 0; n < 8; n++) { e[n] = __expf(lg[rt][n] - mx); sum += e[n]; }
        const float inv = 1.f / sum;
        float* o = (rt == 0 ? o0 : (rt == 1 ? o1 : o2)) + t * 8;
#pragma unroll
        for (int n = 0; n < 8; n++) o[n] = e[n] * inv;
    }
}

// ---------------------------------------------------------------------------
// FUSED expand router + fp16 A' build:
//   ws = softmax(attn[t] . wro);  A'[t, n*512+r] = half(ws[n] * attn[t,r])
// ---------------------------------------------------------------------------
__global__ __launch_bounds__(256) void router_expand_fused(
    const float* __restrict__ attn, const float* __restrict__ wro,
    __half* __restrict__ Aout)
{
    __shared__ float xs[Rz];
    __shared__ float lg[8];
    __shared__ float ws[8];
    const long t = blockIdx.x;
    for (int i = threadIdx.x; i < Rz / 4; i += 256)
        ((float4*)xs)[i] = ((const float4*)(attn + t * Rz))[i];
    __syncthreads();

    const int w = threadIdx.x >> 5;
    const int lane = threadIdx.x & 31;
    {
        const float4* wv4 = (const float4*)(wro + w * Rz);
        float s = 0.f;
#pragma unroll
        for (int i = lane; i < Rz / 4; i += 32) {
            float4 a = ((const float4*)xs)[i];
            float4 b = wv4[i];
            s += a.x * b.x + a.y * b.y + a.z * b.z + a.w * b.w;
        }
#pragma unroll
        for (int off = 16; off; off >>= 1)
            s += __shfl_xor_sync(0xffffffffu, s, off);
        if (lane == 0) lg[w] = s;
    }
    __syncthreads();

    if (threadIdx.x == 0) {
        float mx = lg[0];
#pragma unroll
        for (int n = 1; n < 8; n++) mx = fmaxf(mx, lg[n]);
        float e[8];
        float sum = 0.f;
#pragma unroll
        for (int n = 0; n < 8; n++) { e[n] = __expf(lg[n] - mx); sum += e[n]; }
        const float inv = 1.f / sum;
#pragma unroll
        for (int n = 0; n < 8; n++) ws[n] = e[n] * inv;
    }
    __syncthreads();

    for (int i = threadIdx.x; i < (8 * Rz / 4); i += 256) {
        const int n = i >> 7;
        const int r4 = i & 127;
        float4 a = ((float4*)xs)[r4];
        const float wn = ws[n];
        __half2* dst = (__half2*)(Aout + t * PCOLS + n * Rz) + 2 * r4;
        dst[0] = __floats2half2_rn(a.x * wn, a.y * wn);
        dst[1] = __floats2half2_rn(a.z * wn, a.w * wn);
    }
}

// ---------------------------------------------------------------------------
// q/k/v[t,r] = tf32rnd( sum_n P[t, n*512 + r] * w{q,k,v}[t,n] )  (float4)
// ---------------------------------------------------------------------------
__global__ __launch_bounds__(128) void reduce_qkv(
    const float* __restrict__ P,
    const float* __restrict__ wq, const float* __restrict__ wk,
    const float* __restrict__ wv,
    float* __restrict__ q, float* __restrict__ k, float* __restrict__ v)
{
    const long t = blockIdx.x;
    __shared__ float sq[8], sk[8], sv[8];
    if (threadIdx.x < 8) {
        sq[threadIdx.x] = wq[t * 8 + threadIdx.x];
        sk[threadIdx.x] = wk[t * 8 + threadIdx.x];
        sv[threadIdx.x] = wv[t * 8 + threadIdx.x];
    }
    __syncthreads();
    const float* Pt = P + t * PCOLS;
    const int r4 = threadIdx.x;                 // float4 index 0..127
    float4 aq = make_float4(0.f, 0.f, 0.f, 0.f);
    float4 ak = aq, av = aq;
#pragma unroll
    for (int n = 0; n < 8; n++) {
        const float4 p = ((const float4*)(Pt + n * Rz))[r4];
        const float cq = sq[n], ck = sk[n], cv = sv[n];
        aq.x += p.x * cq; aq.y += p.y * cq; aq.z += p.z * cq; aq.w += p.w * cq;
        ak.x += p.x * ck; ak.y += p.y * ck; ak.z += p.z * ck; ak.w += p.w * ck;
        av.x += p.x * cv; av.y += p.y * cv; av.z += p.z * cv; av.w += p.w * cv;
    }
    ((float4*)(q + t * Rz))[r4] =
        make_float4(tf32r(aq.x), tf32r(aq.y), tf32r(aq.z), tf32r(aq.w));
    ((float4*)(k + t * Rz))[r4] =
        make_float4(tf32r(ak.x), tf32r(ak.y), tf32r(ak.z), tf32r(ak.w));
    ((float4*)(v + t * Rz))[r4] =
        make_float4(tf32r(av.x), tf32r(av.y), tf32r(av.z), tf32r(av.w));
}

// ---------------------------------------------------------------------------
// Tensor-core causal flash attention (tf32 mma.sync), q/k/v pre-rounded.
// K/V tiles double-buffered with cp.async (unchanged from R14).
// ---------------------------------------------------------------------------
#define PADT 68
#define KVSTAGE (2 * 64 * PADT)              // floats per stage (Ks+Vn)
#define ATTN_SMEM ((2 * KVSTAGE + 64 * PADT) * 4)
#define SCALE_L2E 0.1803368801111204f        // (1/sqrt(64)) * log2(e)

__global__ __launch_bounds__(128) void attn_tc_kernel(
    const float* __restrict__ q, const float* __restrict__ k,
    const float* __restrict__ v, float* __restrict__ out)
{
    extern __shared__ __align__(16) float sm[];
    float* Ps = sm + 2 * KVSTAGE;

    const int bh = blockIdx.y;
    const int b = bh >> 3;
    const int h = bh & 7;
    const int qblk = gridDim.x - 1 - blockIdx.x;   // long blocks first
    const int qbase = qblk * 64;
    const int tid = threadIdx.x;
    const int w = tid >> 5;
    const int lane = tid & 31;
    const int g = lane >> 2;
    const int t = lane & 3;

    const float* qb = q + ((long)b * Sz + qbase + w * 16) * Rz + h * DHz;
    uint32_t qf[8][4];
#pragma unroll
    for (int ks = 0; ks < 8; ks++) {
        qf[ks][0] = __float_as_uint(qb[(long)g * Rz + 8 * ks + t]);
        qf[ks][1] = __float_as_uint(qb[(long)(g + 8) * Rz + 8 * ks + t]);
        qf[ks][2] = __float_as_uint(qb[(long)g * Rz + 8 * ks + t + 4]);
        qf[ks][3] = __float_as_uint(qb[(long)(g + 8) * Rz + 8 * ks + t + 4]);
    }

    float Oa[4][2][4];
#pragma unroll
    for (int a = 0; a < 4; a++)
#pragma unroll
        for (int bb = 0; bb < 2; bb++)
#pragma unroll
            for (int c = 0; c < 4; c++) Oa[a][bb][c] = 0.f;
    float m_lo = -1e30f, m_hi = -1e30f, l_lo = 0.f, l_hi = 0.f;

    const float* kb = k + (long)b * Sz * Rz + h * DHz;
    const float* vb = v + (long)b * Sz * Rz + h * DHz;
    const int ntiles = qblk + 1;

    auto loadKV = [&](int tile, int s) {
        float* Kd = sm + s * KVSTAGE;
        float* Vd = Kd + 64 * PADT;
        const long base = (long)(tile * 64);
#pragma unroll
        for (int i = tid; i < 1024; i += 128) {
            const int row = i >> 4;
            const int col = (i & 15) << 2;
            cp_async16(Kd + row * PADT + col, kb + (base + row) * Rz + col);
            cp_async16(Vd + row * PADT + col, vb + (base + row) * Rz + col);
        }
    };

    loadKV(0, 0);
    CP_COMMIT();

    for (int tt = 0; tt < ntiles; tt++) {
        const int s = tt & 1;
        CP_WAIT(0);
        __syncthreads();
        if (tt + 1 < ntiles) {
            loadKV(tt + 1, s ^ 1);
            CP_COMMIT();
        }
        const float* Ks = sm + s * KVSTAGE;
        const float* Vn = Ks + 64 * PADT;

        float S[8][4];
#pragma unroll
        for (int nf = 0; nf < 8; nf++)
#pragma unroll
            for (int c = 0; c < 4; c++) S[nf][c] = 0.f;
#pragma unroll
        for (int ks = 0; ks < 8; ks++) {
            const int c0 = 8 * ks + t, c1 = c0 + 4;
#pragma unroll
            for (int nf = 0; nf < 8; nf++) {
                uint32_t bfr[2];
                bfr[0] = __float_as_uint(Ks[(nf * 8 + g) * PADT + c0]);
                bfr[1] = __float_as_uint(Ks[(nf * 8 + g) * PADT + c1]);
                mma_tf32(S[nf], qf[ks], bfr);
            }
        }

        if (tt == qblk) {
            const int rl = w * 16 + g, rh = rl + 8;
#pragma unroll
            for (int nf = 0; nf < 8; nf++) {
                const int c0 = nf * 8 + 2 * t;
                if (c0 > rl)     S[nf][0] = -1e30f;
                if (c0 + 1 > rl) S[nf][1] = -1e30f;
                if (c0 > rh)     S[nf][2] = -1e30f;
                if (c0 + 1 > rh) S[nf][3] = -1e30f;
            }
        }

        float mx_lo = -1e30f, mx_hi = -1e30f;
#pragma unroll
        for (int nf = 0; nf < 8; nf++) {
            mx_lo = fmaxf(mx_lo, fmaxf(S[nf][0], S[nf][1]));
            mx_hi = fmaxf(mx_hi, fmaxf(S[nf][2], S[nf][3]));
        }
        mx_lo = fmaxf(mx_lo, __shfl_xor_sync(0xffffffffu, mx_lo, 1));
        mx_lo = fmaxf(mx_lo, __shfl_xor_sync(0xffffffffu, mx_lo, 2));
        mx_hi = fmaxf(mx_hi, __shfl_xor_sync(0xffffffffu, mx_hi, 1));
        mx_hi = fmaxf(mx_hi, __shfl_xor_sync(0xffffffffu, mx_hi, 2));

        const float mn_lo = fmaxf(m_lo, mx_lo);
        const float mn_hi = fmaxf(m_hi, mx_hi);
        const float corr_lo = fexp2((m_lo - mn_lo) * SCALE_L2E);
        const float corr_hi = fexp2((m_hi - mn_hi) * SCALE_L2E);
        m_lo = mn_lo; m_hi = mn_hi;
        l_lo *= corr_lo; l_hi *= corr_hi;

        float psum_lo = 0.f, psum_hi = 0.f;
        float* pw = Ps + (w * 16) * PADT;
#pragma unroll
        for (int nf = 0; nf < 8; nf++) {
            const int c0 = nf * 8 + 2 * t;
            float p0 = fexp2((S[nf][0] - mn_lo) * SCALE_L2E);
            float p1 = fexp2((S[nf][1] - mn_lo) * SCALE_L2E);
            float p2 = fexp2((S[nf][2] - mn_hi) * SCALE_L2E);
            float p3 = fexp2((S[nf][3] - mn_hi) * SCALE_L2E);
            psum_lo += p0 + p1;
            psum_hi += p2 + p3;
            *(float2*)(pw + g * PADT + c0) = make_float2(tf32r(p0), tf32r(p1));
            *(float2*)(pw + (g + 8) * PADT + c0) = make_float2(tf32r(p2), tf32r(p3));
        }
        psum_lo += __shfl_xor_sync(0xffffffffu, psum_lo, 1);
        psum_lo += __shfl_xor_sync(0xffffffffu, psum_lo, 2);
        psum_hi += __shfl_xor_sync(0xffffffffu, psum_hi, 1);
        psum_hi += __shfl_xor_sync(0xffffffffu, psum_hi, 2);
        l_lo += psum_lo; l_hi += psum_hi;

        {
            const float cA  = __shfl_sync(0xffffffffu, corr_lo, 8 * t);
            const float cA1 = __shfl_sync(0xffffffffu, corr_lo, 8 * t + 4);
            const float cB  = __shfl_sync(0xffffffffu, corr_hi, 8 * t);
            const float cB1 = __shfl_sync(0xffffffffu, corr_hi, 8 * t + 4);
#pragma unroll
            for (int mt = 0; mt < 4; mt++) {
                Oa[mt][0][0] *= cA;  Oa[mt][0][1] *= cA1;
                Oa[mt][0][2] *= cA;  Oa[mt][0][3] *= cA1;
                Oa[mt][1][0] *= cB;  Oa[mt][1][1] *= cB1;
                Oa[mt][1][2] *= cB;  Oa[mt][1][3] *= cB1;
            }
        }
        __syncwarp();

#pragma unroll
        for (int ks = 0; ks < 8; ks++) {
            const int k0 = 8 * ks + t, k1 = k0 + 4;
            uint32_t bfr[2][2];
#pragma unroll
            for (int nf2 = 0; nf2 < 2; nf2++) {
                bfr[nf2][0] = __float_as_uint(pw[(nf2 * 8 + g) * PADT + k0]);
                bfr[nf2][1] = __float_as_uint(pw[(nf2 * 8 + g) * PADT + k1]);
            }
#pragma unroll
            for (int mt = 0; mt < 4; mt++) {
                uint32_t af[4];
                af[0] = __float_as_uint(Vn[k0 * PADT + mt * 16 + g]);
                af[1] = __float_as_uint(Vn[k0 * PADT + mt * 16 + g + 8]);
                af[2] = __float_as_uint(Vn[k1 * PADT + mt * 16 + g]);
                af[3] = __float_as_uint(Vn[k1 * PADT + mt * 16 + g + 8]);
                mma_tf32(Oa[mt][0], af, bfr[0]);
                mma_tf32(Oa[mt][1], af, bfr[1]);
            }
        }
        __syncwarp();
    }

    const float il_lo = 1.f / l_lo;
    const float il_hi = 1.f / l_hi;
    {
        const float iA  = __shfl_sync(0xffffffffu, il_lo, 8 * t);
        const float iA1 = __shfl_sync(0xffffffffu, il_lo, 8 * t + 4);
        const float iB  = __shfl_sync(0xffffffffu, il_hi, 8 * t);
        const float iB1 = __shfl_sync(0xffffffffu, il_hi, 8 * t + 4);
#pragma unroll
        for (int mt = 0; mt < 4; mt++) {
            Oa[mt][0][0] *= iA;  Oa[mt][0][1] *= iA1;
            Oa[mt][0][2] *= iA;  Oa[mt][0][3] *= iA1;
            Oa[mt][1][0] *= iB;  Oa[mt][1][1] *= iB1;
            Oa[mt][1][2] *= iB;  Oa[mt][1][3] *= iB1;
        }
    }

    float* osm = Ps + (w * 16) * PADT;
    __syncwarp();
#pragma unroll
    for (int mt = 0; mt < 4; mt++) {
#pragma unroll
        for (int nf2 = 0; nf2 < 2; nf2++) {
            const int qc = nf2 * 8 + 2 * t;
            osm[(mt * 16 + g) * 17 + qc]         = Oa[mt][nf2][0];
            osm[(mt * 16 + g) * 17 + qc + 1]     = Oa[mt][nf2][1];
            osm[(mt * 16 + g + 8) * 17 + qc]     = Oa[mt][nf2][2];
            osm[(mt * 16 + g + 8) * 17 + qc + 1] = Oa[mt][nf2][3];
        }
    }
    __syncwarp();
    float* ob = out + ((long)b * Sz + qbase + w * 16) * Rz + h * DHz;
#pragma unroll
    for (int it = 0; it < 8; it++) {
        const int qr = it * 2 + (lane >> 4);
        const int d4 = (lane & 15) << 2;
        float4 vv;
        vv.x = osm[(d4 + 0) * 17 + qr];
        vv.y = osm[(d4 + 1) * 17 + qr];
        vv.z = osm[(d4 + 2) * 17 + qr];
        vv.w = osm[(d4 + 3) * 17 + qr];
        *(float4*)(ob + (long)qr * Rz + d4) = vv;
    }
}

// ---------------------------------------------------------------------------
extern "C" void kernel_launch(void* const* d_in, const int* in_sizes, int n_in,
                              void* d_out, int out_size)
{
    const float* x   = (const float*)d_in[0];
    // d_in[1] = mask: always causal tril -> applied analytically, not read
    const float* CN  = (const float*)d_in[2];  // [NC, D, R]
    const float* EN  = (const float*)d_in[3];  // [NE, R, D]
    const float* wrq = (const float*)d_in[4];
    const float* wrk = (const float*)d_in[5];
    const float* wrv = (const float*)d_in[6];
    const float* wro = (const float*)d_in[7];
    float* out = (float*)d_out;

    float *P, *q, *k, *v, *attn, *wq, *wk, *wv;
    __half *Xh, *Ah, *CNh, *ENh;
    cudaGetSymbolAddress((void**)&P,    g_P);
    cudaGetSymbolAddress((void**)&Xh,   g_Xh);
    cudaGetSymbolAddress((void**)&Ah,   g_Ah);
    cudaGetSymbolAddress((void**)&q,    g_q);
    cudaGetSymbolAddress((void**)&k,    g_k);
    cudaGetSymbolAddress((void**)&v,    g_v);
    cudaGetSymbolAddress((void**)&attn, g_attn);
    cudaGetSymbolAddress((void**)&wq,   g_wq);
    cudaGetSymbolAddress((void**)&wk,   g_wk);
    cudaGetSymbolAddress((void**)&wv,   g_wv);
    cudaGetSymbolAddress((void**)&CNh,  g_CNh);
    cudaGetSymbolAddress((void**)&ENh,  g_ENh);

    cudaFuncSetAttribute(h_gemm,
                         cudaFuncAttributeMaxDynamicSharedMemorySize, GEMM_SMEM_TOTAL);
    cudaFuncSetAttribute(attn_tc_kernel,
                         cudaFuncAttributeMaxDynamicSharedMemorySize, ATTN_SMEM);

    // 0) weights: transpose + fp16 convert
    transpose_h_kernel<<<dim3(Rz / 32, Dz / 32, NCz), 256>>>(
        CN, CNh, Dz, Rz, (long)Dz * Rz, (long)Rz * Dz);
    transpose_h_kernel<<<dim3(Dz / 32, PCOLS / 32, 1), 256>>>(
        EN, ENh, PCOLS, Dz, 0, 0);

    // 1) compress routers (also emits fp16 Xh)
    router_kernel<Dz, 3><<<Tz, 256>>>(x, wrq, wrk, wrv, wq, wk, wv, Xh);

    // 2) P = x @ compress_neurons  (fp16 mma, fp32 accumulate)
    h_gemm<<<dim3(Rz / 128, Tz / 128, NCz), 256, GEMM_SMEM_TOTAL>>>(
        Xh, CNh, P, Dz, Dz, Dz, PCOLS, (long)Rz * Dz, (long)Rz);

    // 3) weighted reduce -> q,k,v (tf32-rounded, float4)
    reduce_qkv<<<Tz, 128>>>(P, wq, wk, wv, q, k, v);

    // 4) causal attention (tf32 tensor cores, cp.async K/V pipeline)
    attn_tc_kernel<<<dim3(Sz / 64, Bz * Hz), 128, ATTN_SMEM>>>(q, k, v, attn);

    // 5+6) fused expand router + fp16 A' build
    router_expand_fused<<<Tz, 256>>>(attn, wro, Ah);

    // 7) out = A' @ expand_neurons  (fp16 mma, fp32 accumulate)
    h_gemm<<<dim3(Dz / 128, Tz / 128, 1), 256, GEMM_SMEM_TOTAL>>>(
        Ah, ENh, out, PCOLS, PCOLS, PCOLS, Dz, 0, 0);
}